// round 14
// baseline (speedup 1.0000x reference)
#include <cuda_runtime.h>
#include <cuda_bf16.h>
#include <cstdint>

// ---------------------------------------------------------------------------
// GAT 2-layer. Layer-0 projection on HMMA (mma.sync bf16, 3-term split),
// 512-thread / 16-warp gemm CTA (occupancy fix: 255 regs -> ~110 regs).
// N = 100000 nodes, E = 1,700,000 edges, dims 1433 -> 140 -> 7
// ---------------------------------------------------------------------------

#define MAXN 100000
#define MAXE 1700000
#define D_IN 1433
#define D_H  140
#define D_O  7

#define NCHUNKS 23            // 23*64 = 1472 >= 1433
#define KPAD    (NCHUNKS * 64)
#define NPAD    144
#define PITCH   72            // bf16 elems per smem row (144B: ldmatrix conflict-free)
#define SA      (128 * PITCH)
#define SB      (NPAD * PITCH)
#define AHI_OFF(b) ((b) * SA)
#define ALO_OFF(b) (2 * SA + (b) * SA)
#define BHI_OFF(b) (4 * SA + (b) * SB)
#define BLO_OFF(b) (4 * SA + 2 * SB + (b) * SB)
#define SM_ELEMS   (4 * SA + 4 * SB)
#define SM_BYTES   (SM_ELEMS * 2)               // 156672

#define GT 512                // gemm threads per CTA (16 warps)

__device__ float g_h0[(size_t)MAXN * D_H];
__device__ float g_h1[(size_t)MAXN * D_H];
__device__ float g_h1p[(size_t)MAXN * D_O];
__device__ float g_el0[MAXN], g_er0[MAXN];
__device__ float g_el1[MAXN], g_er1[MAXN];
__device__ int   g_deg[MAXN];
__device__ int   g_offs[MAXN + 1];
__device__ int   g_cursor[MAXN];
__device__ int   g_ssrc[MAXE];
__device__ int   g_partials[128];
__device__ __nv_bfloat16 g_Bhi[(size_t)NPAD * KPAD];   // W0^T hi image [n][k]
__device__ __nv_bfloat16 g_Blo[(size_t)NPAD * KPAD];   // W0^T lo image

// ---------------- helpers ---------------------------------------------------
__device__ __forceinline__ uint32_t smem_u32(const void* p) {
    return (uint32_t)__cvta_generic_to_shared(p);
}
__device__ __forceinline__ void cp_async16(void* smem, const void* g) {
    asm volatile("cp.async.ca.shared.global [%0], [%1], 16;\n"
                 :: "r"(smem_u32(smem)), "l"(g));
}
__device__ __forceinline__ void cp_commit()   { asm volatile("cp.async.commit_group;\n"); }
__device__ __forceinline__ void cp_wait_all() { asm volatile("cp.async.wait_group 0;\n"); }

__device__ __forceinline__ void ldmx4(uint32_t* r, uint32_t addr) {
    asm volatile("ldmatrix.sync.aligned.m8n8.x4.shared.b16 {%0,%1,%2,%3}, [%4];"
        : "=r"(r[0]), "=r"(r[1]), "=r"(r[2]), "=r"(r[3]) : "r"(addr));
}
__device__ __forceinline__ void ldmx2(uint32_t* r, uint32_t addr) {
    asm volatile("ldmatrix.sync.aligned.m8n8.x2.shared.b16 {%0,%1}, [%2];"
        : "=r"(r[0]), "=r"(r[1]) : "r"(addr));
}
__device__ __forceinline__ void mma_bf16(float* d, const uint32_t* a, const uint32_t* b) {
    asm volatile("mma.sync.aligned.m16n8k16.row.col.f32.bf16.bf16.f32 "
        "{%0,%1,%2,%3}, {%4,%5,%6,%7}, {%8,%9}, {%0,%1,%2,%3};"
        : "+f"(d[0]), "+f"(d[1]), "+f"(d[2]), "+f"(d[3])
        : "r"(a[0]), "r"(a[1]), "r"(a[2]), "r"(a[3]), "r"(b[0]), "r"(b[1]));
}

// ===========================================================================
// Prep: W0^T bf16 hi/lo images, K-contiguous rows (mma col-major B layout).
// ===========================================================================
__global__ void prep_b_kernel(const float* __restrict__ W0) {
    int idx = blockIdx.x * blockDim.x + threadIdx.x;
    if (idx >= NPAD * KPAD) return;
    int n = idx / KPAD, k = idx % KPAD;
    float v = (n < D_H && k < D_IN) ? W0[(size_t)k * D_H + n] : 0.f;
    __nv_bfloat16 h = __float2bfloat16(v);
    g_Bhi[idx] = h;
    g_Blo[idx] = __float2bfloat16(v - __bfloat162float(h));
}

// ===========================================================================
// GEMM0: g_h0 = X @ W0 via mma.sync bf16 3-term split, el0/er0 fused.
// 512 threads / 16 warps, warp tile 16x72 -> 36 accum regs, 2x issue width.
// ===========================================================================
__global__ __launch_bounds__(GT, 1)
void gemm0_mma_kernel(const float* __restrict__ X,
                      const float* __restrict__ al, const float* __restrict__ ar,
                      int Nn)
{
    extern __shared__ __nv_bfloat16 sm[];
    const int tid  = threadIdx.x;
    const int lane = tid & 31, wid = tid >> 5;
    const int m0   = blockIdx.x * 128;
    const int rW   = (wid >> 1) * 16;     // warp row offset (0..112)
    const int nW   = (wid & 1) * 72;      // warp col offset

    float d[9][4];
    #pragma unroll
    for (int nt = 0; nt < 9; ++nt)
        #pragma unroll
        for (int q = 0; q < 4; ++q) d[nt][q] = 0.f;

    float xr[16];

    auto loadB = [&](int c, int buf) {
        #pragma unroll
        for (int q = 0; q < 3; ++q) {
            int idx = tid + q * GT;
            if (idx < NPAD * 8) {
                int n = idx >> 3, j = idx & 7;
                const size_t go = (size_t)n * KPAD + c * 64 + j * 8;
                cp_async16(sm + BHI_OFF(buf) + n * PITCH + j * 8, g_Bhi + go);
                cp_async16(sm + BLO_OFF(buf) + n * PITCH + j * 8, g_Blo + go);
            }
        }
    };
    auto loadX = [&](int c) {
        const int k0 = c * 64;
        #pragma unroll
        for (int j = 0; j < 16; ++j) {
            int i = tid + j * GT;
            int row = i >> 6, col = i & 63;
            int gm = m0 + row, k = k0 + col;
            xr[j] = (gm < Nn && k < D_IN) ? __ldg(X + (size_t)gm * D_IN + k) : 0.f;
        }
    };
    auto storeA = [&](int buf) {
        const bool odd = lane & 1;
        #pragma unroll
        for (int j = 0; j < 16; ++j) {
            int i = tid + j * GT;
            int row = i >> 6, col = i & 63;
            float v  = xr[j];
            float vp = __shfl_xor_sync(0xffffffffu, v, 1);
            float v0 = odd ? vp : v;
            float v1 = odd ? v : vp;
            __nv_bfloat162 h2 = __floats2bfloat162_rn(v0, v1);
            int c0 = col & ~1;
            if (!odd) {
                *(__nv_bfloat162*)(sm + AHI_OFF(buf) + row * PITCH + c0) = h2;
            } else {
                float l0 = v0 - __bfloat162float(h2.x);
                float l1 = v1 - __bfloat162float(h2.y);
                *(__nv_bfloat162*)(sm + ALO_OFF(buf) + row * PITCH + c0) =
                    __floats2bfloat162_rn(l0, l1);
            }
        }
    };
    auto compute = [&](int buf) {
        const uint32_t aH = smem_u32(sm + AHI_OFF(buf));
        const uint32_t aL = smem_u32(sm + ALO_OFF(buf));
        const uint32_t bH = smem_u32(sm + BHI_OFF(buf));
        const uint32_t bL = smem_u32(sm + BLO_OFF(buf));
        #pragma unroll
        for (int ks = 0; ks < 4; ++ks) {
            const int k0 = ks * 16;
            uint32_t ah[4], al_[4];
            {
                uint32_t off = ((rW + (lane & 15)) * PITCH
                                + k0 + (lane >> 4) * 8) * 2;
                ldmx4(ah,  aH + off);
                ldmx4(al_, aL + off);
            }
            #pragma unroll
            for (int nt = 0; nt < 9; ++nt) {
                uint32_t boff = ((nW + nt * 8 + (lane & 7)) * PITCH
                                 + k0 + ((lane >> 3) & 1) * 8) * 2;
                uint32_t bh[2], bl[2];
                ldmx2(bh, bH + boff);
                ldmx2(bl, bL + boff);
                mma_bf16(d[nt], ah,  bh);
                mma_bf16(d[nt], al_, bh);
                mma_bf16(d[nt], ah,  bl);
            }
        }
    };

    loadB(0, 0); cp_commit();
    loadX(0); storeA(0);

    for (int c = 0; c < NCHUNKS; ++c) {
        const int buf = c & 1;
        cp_wait_all();
        __syncthreads();
        if (c + 1 < NCHUNKS) { loadB(c + 1, buf ^ 1); cp_commit(); loadX(c + 1); }
        compute(buf);
        if (c + 1 < NCHUNKS) storeA(buf ^ 1);
    }

    // ---- epilogue: store h0 rows + fused el/er partials --------------------
    float pel[2] = {0.f, 0.f};    // rows mr, mr+8
    float per[2] = {0.f, 0.f};
    const int mr = m0 + rW + (lane >> 2);

    #pragma unroll
    for (int nt = 0; nt < 9; ++nt) {
        int n = nW + nt * 8 + (lane & 3) * 2;
        float al0v = (n     < D_H) ? __ldg(al + n)     : 0.f;
        float al1v = (n + 1 < D_H) ? __ldg(al + n + 1) : 0.f;
        float ar0v = (n     < D_H) ? __ldg(ar + n)     : 0.f;
        float ar1v = (n + 1 < D_H) ? __ldg(ar + n + 1) : 0.f;
        pel[0] += d[nt][0] * al0v + d[nt][1] * al1v;
        pel[1] += d[nt][2] * al0v + d[nt][3] * al1v;
        per[0] += d[nt][0] * ar0v + d[nt][1] * ar1v;
        per[1] += d[nt][2] * ar0v + d[nt][3] * ar1v;
        if (n < D_H) {
            if (mr < Nn)
                *(float2*)(g_h0 + (size_t)mr * D_H + n) = make_float2(d[nt][0], d[nt][1]);
            if (mr + 8 < Nn)
                *(float2*)(g_h0 + (size_t)(mr + 8) * D_H + n) = make_float2(d[nt][2], d[nt][3]);
        }
    }
    #pragma unroll
    for (int rr = 0; rr < 2; ++rr) {
        #pragma unroll
        for (int o = 1; o < 4; o <<= 1) {
            pel[rr] += __shfl_xor_sync(0xffffffffu, pel[rr], o);
            per[rr] += __shfl_xor_sync(0xffffffffu, per[rr], o);
        }
    }
    if ((lane & 3) == 0) {
        if (mr < Nn)     { atomicAdd(&g_el0[mr],     pel[0]); atomicAdd(&g_er0[mr],     per[0]); }
        if (mr + 8 < Nn) { atomicAdd(&g_el0[mr + 8], pel[1]); atomicAdd(&g_er0[mr + 8], per[1]); }
    }
}

// ===========================================================================
// CSR build (zero_all also zeroes el0/er0 accumulated by gemm epilogue)
// ===========================================================================
__global__ void zero_all_kernel(int n) {
    int i = blockIdx.x * blockDim.x + threadIdx.x;
    if (i < n) { g_deg[i] = 0; g_el0[i] = 0.f; g_er0[i] = 0.f; }
}
__global__ void count_kernel(const int* __restrict__ dst, int e) {
    int i = blockIdx.x * blockDim.x + threadIdx.x;
    if (i < e) atomicAdd(&g_deg[dst[i]], 1);
}
__global__ void scan_chunk_sums_kernel(int n) {
    int b = blockIdx.x, t = threadIdx.x;
    int base = b * 1024 + t * 4;
    int s = 0;
    #pragma unroll
    for (int i = 0; i < 4; ++i) { int idx = base + i; if (idx < n) s += g_deg[idx]; }
    __shared__ int wsum[8];
    for (int o = 16; o; o >>= 1) s += __shfl_xor_sync(0xffffffffu, s, o);
    if ((t & 31) == 0) wsum[t >> 5] = s;
    __syncthreads();
    if (t == 0) {
        int tot = 0;
        #pragma unroll
        for (int i = 0; i < 8; ++i) tot += wsum[i];
        g_partials[b] = tot;
    }
}
__global__ void scan_partials_kernel(int nch, int n, int e) {
    if (threadIdx.x == 0) {
        int acc = 0;
        for (int i = 0; i < nch; ++i) { int v = g_partials[i]; g_partials[i] = acc; acc += v; }
        g_offs[n] = e;
    }
}
__global__ void scan_final_kernel(int n) {
    int b = blockIdx.x, t = threadIdx.x;
    int base = b * 1024 + t * 4;
    int v[4]; int s = 0;
    #pragma unroll
    for (int i = 0; i < 4; ++i) { int idx = base + i; v[i] = (idx < n) ? g_deg[idx] : 0; s += v[i]; }
    __shared__ int wsum[8];
    int lane = t & 31, wid = t >> 5;
    int inc = s;
    for (int o = 1; o < 32; o <<= 1) {
        int tv = __shfl_up_sync(0xffffffffu, inc, o);
        if (lane >= o) inc += tv;
    }
    if (lane == 31) wsum[wid] = inc;
    __syncthreads();
    int woff = 0;
    for (int i = 0; i < wid; ++i) woff += wsum[i];
    int ex = woff + inc - s + g_partials[b];
    #pragma unroll
    for (int i = 0; i < 4; ++i) {
        int idx = base + i;
        if (idx < n) { g_offs[idx] = ex; g_cursor[idx] = ex; ex += v[i]; }
    }
}
__global__ void fill_kernel(const int* __restrict__ src, const int* __restrict__ dst, int e) {
    int i = blockIdx.x * blockDim.x + threadIdx.x;
    if (i < e) { int p = atomicAdd(&g_cursor[dst[i]], 1); g_ssrc[p] = src[i]; }
}

// ===========================================================================
// Aggregation D=140: warp per dst node; online softmax, then float4 gather.
// ===========================================================================
__global__ void aggregate140_kernel(const float* __restrict__ h,
                                    const float* __restrict__ el,
                                    const float* __restrict__ er,
                                    const float* __restrict__ bias,
                                    float* __restrict__ out, int n)
{
    int w = (blockIdx.x * blockDim.x + threadIdx.x) >> 5;
    int lane = threadIdx.x & 31;
    if (w >= n) return;
    const int start = g_offs[w], end = g_offs[w + 1];
    const float er_i = er[w];

    float m = -1e30f, s = 0.f;
    for (int e = start + lane; e < end; e += 32) {
        int sj = g_ssrc[e];
        float v = el[sj] + er_i;
        v = (v > 0.f) ? v : 0.2f * v;
        float nm = fmaxf(m, v);
        s = s * __expf(m - nm) + __expf(v - nm);
        m = nm;
    }
    for (int o = 16; o; o >>= 1) {
        float om = __shfl_xor_sync(0xffffffffu, m, o);
        float os = __shfl_xor_sync(0xffffffffu, s, o);
        float nm = fmaxf(m, om);
        s = s * __expf(m - nm) + os * __expf(om - nm);
        m = nm;
    }
    const float inv = 1.f / s;

    float4 acc  = make_float4(0.f, 0.f, 0.f, 0.f);
    float4 accx = make_float4(0.f, 0.f, 0.f, 0.f);   // lanes 0-2: cols 128..139

    for (int e0 = start; e0 < end; e0 += 32) {
        int e = e0 + lane;
        int sj = 0; float a = 0.f;
        if (e < end) {
            sj = g_ssrc[e];
            float v = el[sj] + er_i;
            v = (v > 0.f) ? v : 0.2f * v;
            a = __expf(v - m) * inv;
        }
        int cnt = min(32, end - e0);
        for (int j = 0; j < cnt; ++j) {
            int   sje = __shfl_sync(0xffffffffu, sj, j);
            float aje = __shfl_sync(0xffffffffu, a, j);
            const float4* hp = (const float4*)(h + (size_t)sje * D_H);
            float4 v = hp[lane];
            acc.x += aje * v.x; acc.y += aje * v.y;
            acc.z += aje * v.z; acc.w += aje * v.w;
            if (lane < 3) {
                float4 v2 = hp[32 + lane];
                accx.x += aje * v2.x; accx.y += aje * v2.y;
                accx.z += aje * v2.z; accx.w += aje * v2.w;
            }
        }
    }

    const float4* b4 = (const float4*)bias;
    float4 bb = b4[lane];
    float4 r  = make_float4(fmaxf(acc.x + bb.x, 0.f), fmaxf(acc.y + bb.y, 0.f),
                            fmaxf(acc.z + bb.z, 0.f), fmaxf(acc.w + bb.w, 0.f));
    ((float4*)(out + (size_t)w * D_H))[lane] = r;
    if (lane < 3) {
        float4 bb2 = b4[32 + lane];
        float4 r2  = make_float4(fmaxf(accx.x + bb2.x, 0.f), fmaxf(accx.y + bb2.y, 0.f),
                                 fmaxf(accx.z + bb2.z, 0.f), fmaxf(accx.w + bb2.w, 0.f));
        ((float4*)(out + (size_t)w * D_H))[32 + lane] = r2;
    }
}

// ===========================================================================
// Aggregation D=7 (layer 1 output)
// ===========================================================================
__global__ void aggregate7_kernel(const float* __restrict__ h,
                                  const float* __restrict__ el,
                                  const float* __restrict__ er,
                                  const float* __restrict__ bias,
                                  float* __restrict__ out, int n)
{
    int w = (blockIdx.x * blockDim.x + threadIdx.x) >> 5;
    int lane = threadIdx.x & 31;
    if (w >= n) return;
    const int start = g_offs[w], end = g_offs[w + 1];
    const float er_i = er[w];

    float m = -1e30f, s = 0.f;
    for (int e = start + lane; e < end; e += 32) {
        int sj = g_ssrc[e];
        float v = el[sj] + er_i;
        v = (v > 0.f) ? v : 0.2f * v;
        float nm = fmaxf(m, v);
        s = s * __expf(m - nm) + __expf(v - nm);
        m = nm;
    }
    for (int o = 16; o; o >>= 1) {
        float om = __shfl_xor_sync(0xffffffffu, m, o);
        float os = __shfl_xor_sync(0xffffffffu, s, o);
        float nm = fmaxf(m, om);
        s = s * __expf(m - nm) + os * __expf(om - nm);
        m = nm;
    }
    const float inv = 1.f / s;

    float acc = 0.f;
    for (int e0 = start; e0 < end; e0 += 32) {
        int e = e0 + lane;
        int sj = 0; float a = 0.f;
        if (e < end) {
            sj = g_ssrc[e];
            float v = el[sj] + er_i;
            v = (v > 0.f) ? v : 0.2f * v;
            a = __expf(v - m) * inv;
        }
        int cnt = min(32, end - e0);
        for (int j = 0; j < cnt; ++j) {
            int   sje = __shfl_sync(0xffffffffu, sj, j);
            float aje = __shfl_sync(0xffffffffu, a, j);
            if (lane < D_O) acc += aje * h[(size_t)sje * D_O + lane];
        }
    }
    if (lane < D_O) out[(size_t)w * D_O + lane] = fmaxf(acc + bias[lane], 0.f);
}

// ===========================================================================
// Layer-1 projection (140 -> 7) + el1/er1
// ===========================================================================
__global__ void proj1_kernel(const float* __restrict__ h1, const float* __restrict__ W1,
                             const float* __restrict__ al1, const float* __restrict__ ar1,
                             float* __restrict__ h1p, float* __restrict__ el1,
                             float* __restrict__ er1, int n)
{
    __shared__ float Wt[D_O * D_H];
    __shared__ float als[D_O], ars[D_O];
    for (int i = threadIdx.x; i < D_H * D_O; i += blockDim.x) {
        int c = i / D_O, j = i % D_O;
        Wt[j * D_H + c] = W1[i];
    }
    if (threadIdx.x < D_O) { als[threadIdx.x] = al1[threadIdx.x]; ars[threadIdx.x] = ar1[threadIdx.x]; }
    __syncthreads();

    int w = (blockIdx.x * blockDim.x + threadIdx.x) >> 5;
    int lane = threadIdx.x & 31;
    if (w >= n) return;

    float p[D_O];
    #pragma unroll
    for (int j = 0; j < D_O; ++j) p[j] = 0.f;

    const float* hr = h1 + (size_t)w * D_H;
    for (int c = lane; c < D_H; c += 32) {
        float hc = hr[c];
        #pragma unroll
        for (int j = 0; j < D_O; ++j) p[j] += hc * Wt[j * D_H + c];
    }
    #pragma unroll
    for (int j = 0; j < D_O; ++j)
        for (int o = 16; o; o >>= 1) p[j] += __shfl_xor_sync(0xffffffffu, p[j], o);

    if (lane == 0) {
        float elv = 0.f, erv = 0.f;
        float* op = h1p + (size_t)w * D_O;
        #pragma unroll
        for (int j = 0; j < D_O; ++j) {
            op[j] = p[j];
            elv += p[j] * als[j];
            erv += p[j] * ars[j];
        }
        el1[w] = elv;
        er1[w] = erv;
    }
}

// ===========================================================================
// launch
// ===========================================================================
extern "C" void kernel_launch(void* const* d_in, const int* in_sizes, int n_in,
                              void* d_out, int out_size)
{
    const float* X = nullptr;  const int* src = nullptr; const int* dst = nullptr;
    const float* W0 = nullptr; const float* al0 = nullptr; const float* ar0 = nullptr;
    const float* b0 = nullptr; const float* W1 = nullptr; const float* al1 = nullptr;
    const float* ar1 = nullptr; const float* b1 = nullptr;

    for (int i = 0; i < n_in; ++i) {
        long long s = in_sizes[i];
        void* p = d_in[i];
        if      (s == (long long)MAXN * D_IN) X  = (const float*)p;
        else if (s == (long long)MAXE) { if (!src) src = (const int*)p; else dst = (const int*)p; }
        else if (s == (long long)D_IN * D_H) W0 = (const float*)p;
        else if (s == (long long)D_H * D_O)  W1 = (const float*)p;
        else if (s == D_H) { if (!al0) al0 = (const float*)p; else if (!ar0) ar0 = (const float*)p; else b0 = (const float*)p; }
        else if (s == D_O) { if (!al1) al1 = (const float*)p; else if (!ar1) ar1 = (const float*)p; else b1 = (const float*)p; }
    }
    if (!X || !src || !dst || !W0 || !al0 || !ar0 || !b0 || !W1 || !al1 || !ar1 || !b1) {
        X   = (const float*)d_in[0];  src = (const int*)d_in[1];  dst = (const int*)d_in[2];
        W0  = (const float*)d_in[3];  al0 = (const float*)d_in[4]; ar0 = (const float*)d_in[5];
        b0  = (const float*)d_in[6];  W1  = (const float*)d_in[7]; al1 = (const float*)d_in[8];
        ar1 = (const float*)d_in[9];  b1  = (const float*)d_in[10];
    }
    float* out = (float*)d_out;

    float *h0, *h1, *h1p, *el0, *er0, *el1, *er1;
    cudaGetSymbolAddress((void**)&h0,  g_h0);
    cudaGetSymbolAddress((void**)&h1,  g_h1);
    cudaGetSymbolAddress((void**)&h1p, g_h1p);
    cudaGetSymbolAddress((void**)&el0, g_el0);
    cudaGetSymbolAddress((void**)&er0, g_er0);
    cudaGetSymbolAddress((void**)&el1, g_el1);
    cudaGetSymbolAddress((void**)&er1, g_er1);

    const int N = [&]{
        for (int i = 0; i < n_in; ++i) if (in_sizes[i] % D_IN == 0 && in_sizes[i] > 1000000) return in_sizes[i] / D_IN;
        return MAXN; }();
    int E = MAXE;
    for (int i = 0; i < n_in; ++i) if ((const void*)d_in[i] == (const void*)src) { E = in_sizes[i]; break; }

    cudaFuncSetAttribute(gemm0_mma_kernel, cudaFuncAttributeMaxDynamicSharedMemorySize, SM_BYTES);

    const int TB = 256;
    const int nwarp_blocks = (N + 7) / 8;
    const int nch = (N + 1023) / 1024;

    // Harness inserts ~2 kernels before ours; ncu -s 5 lands on launch idx 3.
    prep_b_kernel<<<(NPAD * KPAD + 255) / 256, 256>>>(W0);                   // 0
    zero_all_kernel<<<(N + TB - 1) / TB, TB>>>(N);                           // 1
    count_kernel<<<(E + TB - 1) / TB, TB>>>(dst, E);                         // 2
    gemm0_mma_kernel<<<(N + 127) / 128, GT, SM_BYTES>>>(X, al0, ar0, N);     // 3 <- ncu
    scan_chunk_sums_kernel<<<nch, TB>>>(N);                                  // 4
    scan_partials_kernel<<<1, 32>>>(nch, N, E);                              // 5
    scan_final_kernel<<<nch, TB>>>(N);                                       // 6
    fill_kernel<<<(E + TB - 1) / TB, TB>>>(src, dst, E);                     // 7
    aggregate140_kernel<<<nwarp_blocks, TB>>>(h0, el0, er0, b0, h1, N);      // 8
    proj1_kernel<<<nwarp_blocks, TB>>>(h1, W1, al1, ar1, h1p, el1, er1, N);  // 9
    aggregate7_kernel<<<nwarp_blocks, TB>>>(h1p, el1, er1, b1, out, N);      // 10
}

// round 15
// speedup vs baseline: 1.6770x; 1.6770x over previous
#include <cuda_runtime.h>
#include <cuda_bf16.h>
#include <cstdint>

// ---------------------------------------------------------------------------
// GAT 2-layer. Layer-0 projection on HMMA (mma.sync bf16, 3-term split).
// R15: ldmatrix.x4 for B fragments (n16k16 per op) -> LDSM ops 80->48/warp-chunk.
// N = 100000 nodes, E = 1,700,000 edges, dims 1433 -> 140 -> 7
// ---------------------------------------------------------------------------

#define MAXN 100000
#define MAXE 1700000
#define D_IN 1433
#define D_H  140
#define D_O  7

#define NCHUNKS 23            // 23*64 = 1472 >= 1433
#define KPAD    (NCHUNKS * 64)
#define NPAD    144
#define PITCH   72            // bf16 elems per smem row (144B: ldmatrix conflict-free)
#define SA      (128 * PITCH)
#define SB      (NPAD * PITCH)
#define AHI_OFF(b) ((b) * SA)
#define ALO_OFF(b) (2 * SA + (b) * SA)
#define BHI_OFF(b) (4 * SA + (b) * SB)
#define BLO_OFF(b) (4 * SA + 2 * SB + (b) * SB)
#define SM_ELEMS   (4 * SA + 4 * SB)
#define SM_BYTES   (SM_ELEMS * 2)               // 156672

#define GT 512                // gemm threads per CTA (16 warps)

__device__ float g_h0[(size_t)MAXN * D_H];
__device__ float g_h1[(size_t)MAXN * D_H];
__device__ float g_h1p[(size_t)MAXN * D_O];
__device__ float g_el0[MAXN], g_er0[MAXN];
__device__ float g_el1[MAXN], g_er1[MAXN];
__device__ int   g_deg[MAXN];
__device__ int   g_offs[MAXN + 1];
__device__ int   g_cursor[MAXN];
__device__ int   g_ssrc[MAXE];
__device__ int   g_partials[128];
__device__ __nv_bfloat16 g_Bhi[(size_t)NPAD * KPAD];   // W0^T hi image [n][k]
__device__ __nv_bfloat16 g_Blo[(size_t)NPAD * KPAD];   // W0^T lo image

// ---------------- helpers ---------------------------------------------------
__device__ __forceinline__ uint32_t smem_u32(const void* p) {
    return (uint32_t)__cvta_generic_to_shared(p);
}
__device__ __forceinline__ void cp_async16(void* smem, const void* g) {
    asm volatile("cp.async.ca.shared.global [%0], [%1], 16;\n"
                 :: "r"(smem_u32(smem)), "l"(g));
}
__device__ __forceinline__ void cp_commit()   { asm volatile("cp.async.commit_group;\n"); }
__device__ __forceinline__ void cp_wait_all() { asm volatile("cp.async.wait_group 0;\n"); }

__device__ __forceinline__ void ldmx4(uint32_t* r, uint32_t addr) {
    asm volatile("ldmatrix.sync.aligned.m8n8.x4.shared.b16 {%0,%1,%2,%3}, [%4];"
        : "=r"(r[0]), "=r"(r[1]), "=r"(r[2]), "=r"(r[3]) : "r"(addr));
}
__device__ __forceinline__ void ldmx2(uint32_t* r, uint32_t addr) {
    asm volatile("ldmatrix.sync.aligned.m8n8.x2.shared.b16 {%0,%1}, [%2];"
        : "=r"(r[0]), "=r"(r[1]) : "r"(addr));
}
__device__ __forceinline__ void mma_bf16(float* d, const uint32_t* a, const uint32_t* b) {
    asm volatile("mma.sync.aligned.m16n8k16.row.col.f32.bf16.bf16.f32 "
        "{%0,%1,%2,%3}, {%4,%5,%6,%7}, {%8,%9}, {%0,%1,%2,%3};"
        : "+f"(d[0]), "+f"(d[1]), "+f"(d[2]), "+f"(d[3])
        : "r"(a[0]), "r"(a[1]), "r"(a[2]), "r"(a[3]), "r"(b[0]), "r"(b[1]));
}

// ===========================================================================
// Prep: W0^T bf16 hi/lo images, K-contiguous rows (mma col-major B layout).
// ===========================================================================
__global__ void prep_b_kernel(const float* __restrict__ W0) {
    int idx = blockIdx.x * blockDim.x + threadIdx.x;
    if (idx >= NPAD * KPAD) return;
    int n = idx / KPAD, k = idx % KPAD;
    float v = (n < D_H && k < D_IN) ? W0[(size_t)k * D_H + n] : 0.f;
    __nv_bfloat16 h = __float2bfloat16(v);
    g_Bhi[idx] = h;
    g_Blo[idx] = __float2bfloat16(v - __bfloat162float(h));
}

// ===========================================================================
// GEMM0: g_h0 = X @ W0 via mma.sync bf16 3-term split, el0/er0 fused.
// 512 threads / 16 warps; warp tile 16x72; B fragments via ldmatrix.x4.
// ===========================================================================
__global__ __launch_bounds__(GT, 1)
void gemm0_mma_kernel(const float* __restrict__ X,
                      const float* __restrict__ al, const float* __restrict__ ar,
                      int Nn)
{
    extern __shared__ __nv_bfloat16 sm[];
    const int tid  = threadIdx.x;
    const int lane = tid & 31, wid = tid >> 5;
    const int m0   = blockIdx.x * 128;
    const int rW   = (wid >> 1) * 16;     // warp row offset (0..112)
    const int nW   = (wid & 1) * 72;      // warp col offset

    // ldmatrix.x4 B addressing: matrices [ (n0:8,k0:8), (n0:8,k8:16),
    //                                      (n8:16,k0:8), (n8:16,k8:16) ]
    const int bgrp  = lane >> 3;
    const int bnoff = (bgrp >> 1) * 8 + (lane & 7);
    const int bkoff = (bgrp & 1) * 8;

    float d[9][4];
    #pragma unroll
    for (int nt = 0; nt < 9; ++nt)
        #pragma unroll
        for (int q = 0; q < 4; ++q) d[nt][q] = 0.f;

    float xr[16];

    auto loadB = [&](int c, int buf) {
        #pragma unroll
        for (int q = 0; q < 3; ++q) {
            int idx = tid + q * GT;
            if (idx < NPAD * 8) {
                int n = idx >> 3, j = idx & 7;
                const size_t go = (size_t)n * KPAD + c * 64 + j * 8;
                cp_async16(sm + BHI_OFF(buf) + n * PITCH + j * 8, g_Bhi + go);
                cp_async16(sm + BLO_OFF(buf) + n * PITCH + j * 8, g_Blo + go);
            }
        }
    };
    auto loadX = [&](int c) {
        const int k0 = c * 64;
        #pragma unroll
        for (int j = 0; j < 16; ++j) {
            int i = tid + j * GT;
            int row = i >> 6, col = i & 63;
            int gm = m0 + row, k = k0 + col;
            xr[j] = (gm < Nn && k < D_IN) ? __ldg(X + (size_t)gm * D_IN + k) : 0.f;
        }
    };
    auto storeA = [&](int buf) {
        const bool odd = lane & 1;
        #pragma unroll
        for (int j = 0; j < 16; ++j) {
            int i = tid + j * GT;
            int row = i >> 6, col = i & 63;
            float v  = xr[j];
            float vp = __shfl_xor_sync(0xffffffffu, v, 1);
            float v0 = odd ? vp : v;
            float v1 = odd ? v : vp;
            __nv_bfloat162 h2 = __floats2bfloat162_rn(v0, v1);
            int c0 = col & ~1;
            if (!odd) {
                *(__nv_bfloat162*)(sm + AHI_OFF(buf) + row * PITCH + c0) = h2;
            } else {
                float l0 = v0 - __bfloat162float(h2.x);
                float l1 = v1 - __bfloat162float(h2.y);
                *(__nv_bfloat162*)(sm + ALO_OFF(buf) + row * PITCH + c0) =
                    __floats2bfloat162_rn(l0, l1);
            }
        }
    };
    auto compute = [&](int buf) {
        const uint32_t aH = smem_u32(sm + AHI_OFF(buf));
        const uint32_t aL = smem_u32(sm + ALO_OFF(buf));
        const uint32_t bH = smem_u32(sm + BHI_OFF(buf));
        const uint32_t bL = smem_u32(sm + BLO_OFF(buf));
        #pragma unroll
        for (int ks = 0; ks < 4; ++ks) {
            const int k0 = ks * 16;
            uint32_t ah[4], al_[4];
            {
                uint32_t off = ((rW + (lane & 15)) * PITCH
                                + k0 + (lane >> 4) * 8) * 2;
                ldmx4(ah,  aH + off);
                ldmx4(al_, aL + off);
            }
            // n-tile pairs via x4 (covers nt=2p, 2p+1)
            #pragma unroll
            for (int p = 0; p < 4; ++p) {
                uint32_t boff = ((nW + p * 16 + bnoff) * PITCH + k0 + bkoff) * 2;
                uint32_t bh4[4], bl4[4];
                ldmx4(bh4, bH + boff);
                ldmx4(bl4, bL + boff);
                mma_bf16(d[2*p],     ah,  bh4);
                mma_bf16(d[2*p],     al_, bh4);
                mma_bf16(d[2*p],     ah,  bl4);
                mma_bf16(d[2*p + 1], ah,  bh4 + 2);
                mma_bf16(d[2*p + 1], al_, bh4 + 2);
                mma_bf16(d[2*p + 1], ah,  bl4 + 2);
            }
            // tail n-tile nt=8 via x2
            {
                uint32_t boff = ((nW + 64 + (lane & 7)) * PITCH
                                 + k0 + ((lane >> 3) & 1) * 8) * 2;
                uint32_t bh[2], bl[2];
                ldmx2(bh, bH + boff);
                ldmx2(bl, bL + boff);
                mma_bf16(d[8], ah,  bh);
                mma_bf16(d[8], al_, bh);
                mma_bf16(d[8], ah,  bl);
            }
        }
    };

    loadB(0, 0); cp_commit();
    loadX(0); storeA(0);

    for (int c = 0; c < NCHUNKS; ++c) {
        const int buf = c & 1;
        cp_wait_all();
        __syncthreads();
        if (c + 1 < NCHUNKS) { loadB(c + 1, buf ^ 1); cp_commit(); loadX(c + 1); }
        compute(buf);
        if (c + 1 < NCHUNKS) storeA(buf ^ 1);
    }

    // ---- epilogue: store h0 rows + fused el/er partials --------------------
    float pel[2] = {0.f, 0.f};    // rows mr, mr+8
    float per[2] = {0.f, 0.f};
    const int mr = m0 + rW + (lane >> 2);

    #pragma unroll
    for (int nt = 0; nt < 9; ++nt) {
        int n = nW + nt * 8 + (lane & 3) * 2;
        float al0v = (n     < D_H) ? __ldg(al + n)     : 0.f;
        float al1v = (n + 1 < D_H) ? __ldg(al + n + 1) : 0.f;
        float ar0v = (n     < D_H) ? __ldg(ar + n)     : 0.f;
        float ar1v = (n + 1 < D_H) ? __ldg(ar + n + 1) : 0.f;
        pel[0] += d[nt][0] * al0v + d[nt][1] * al1v;
        pel[1] += d[nt][2] * al0v + d[nt][3] * al1v;
        per[0] += d[nt][0] * ar0v + d[nt][1] * ar1v;
        per[1] += d[nt][2] * ar0v + d[nt][3] * ar1v;
        if (n < D_H) {
            if (mr < Nn)
                *(float2*)(g_h0 + (size_t)mr * D_H + n) = make_float2(d[nt][0], d[nt][1]);
            if (mr + 8 < Nn)
                *(float2*)(g_h0 + (size_t)(mr + 8) * D_H + n) = make_float2(d[nt][2], d[nt][3]);
        }
    }
    #pragma unroll
    for (int rr = 0; rr < 2; ++rr) {
        #pragma unroll
        for (int o = 1; o < 4; o <<= 1) {
            pel[rr] += __shfl_xor_sync(0xffffffffu, pel[rr], o);
            per[rr] += __shfl_xor_sync(0xffffffffu, per[rr], o);
        }
    }
    if ((lane & 3) == 0) {
        if (mr < Nn)     { atomicAdd(&g_el0[mr],     pel[0]); atomicAdd(&g_er0[mr],     per[0]); }
        if (mr + 8 < Nn) { atomicAdd(&g_el0[mr + 8], pel[1]); atomicAdd(&g_er0[mr + 8], per[1]); }
    }
}

// ===========================================================================
// CSR build (zero_all also zeroes el0/er0 accumulated by gemm epilogue)
// ===========================================================================
__global__ void zero_all_kernel(int n) {
    int i = blockIdx.x * blockDim.x + threadIdx.x;
    if (i < n) { g_deg[i] = 0; g_el0[i] = 0.f; g_er0[i] = 0.f; }
}
__global__ void count_kernel(const int* __restrict__ dst, int e) {
    int i = blockIdx.x * blockDim.x + threadIdx.x;
    if (i < e) atomicAdd(&g_deg[dst[i]], 1);
}
__global__ void scan_chunk_sums_kernel(int n) {
    int b = blockIdx.x, t = threadIdx.x;
    int base = b * 1024 + t * 4;
    int s = 0;
    #pragma unroll
    for (int i = 0; i < 4; ++i) { int idx = base + i; if (idx < n) s += g_deg[idx]; }
    __shared__ int wsum[8];
    for (int o = 16; o; o >>= 1) s += __shfl_xor_sync(0xffffffffu, s, o);
    if ((t & 31) == 0) wsum[t >> 5] = s;
    __syncthreads();
    if (t == 0) {
        int tot = 0;
        #pragma unroll
        for (int i = 0; i < 8; ++i) tot += wsum[i];
        g_partials[b] = tot;
    }
}
__global__ void scan_partials_kernel(int nch, int n, int e) {
    if (threadIdx.x == 0) {
        int acc = 0;
        for (int i = 0; i < nch; ++i) { int v = g_partials[i]; g_partials[i] = acc; acc += v; }
        g_offs[n] = e;
    }
}
__global__ void scan_final_kernel(int n) {
    int b = blockIdx.x, t = threadIdx.x;
    int base = b * 1024 + t * 4;
    int v[4]; int s = 0;
    #pragma unroll
    for (int i = 0; i < 4; ++i) { int idx = base + i; v[i] = (idx < n) ? g_deg[idx] : 0; s += v[i]; }
    __shared__ int wsum[8];
    int lane = t & 31, wid = t >> 5;
    int inc = s;
    for (int o = 1; o < 32; o <<= 1) {
        int tv = __shfl_up_sync(0xffffffffu, inc, o);
        if (lane >= o) inc += tv;
    }
    if (lane == 31) wsum[wid] = inc;
    __syncthreads();
    int woff = 0;
    for (int i = 0; i < wid; ++i) woff += wsum[i];
    int ex = woff + inc - s + g_partials[b];
    #pragma unroll
    for (int i = 0; i < 4; ++i) {
        int idx = base + i;
        if (idx < n) { g_offs[idx] = ex; g_cursor[idx] = ex; ex += v[i]; }
    }
}
__global__ void fill_kernel(const int* __restrict__ src, const int* __restrict__ dst, int e) {
    int i = blockIdx.x * blockDim.x + threadIdx.x;
    if (i < e) { int p = atomicAdd(&g_cursor[dst[i]], 1); g_ssrc[p] = src[i]; }
}

// ===========================================================================
// Aggregation D=140: warp per dst node; online softmax, then float4 gather.
// ===========================================================================
__global__ void aggregate140_kernel(const float* __restrict__ h,
                                    const float* __restrict__ el,
                                    const float* __restrict__ er,
                                    const float* __restrict__ bias,
                                    float* __restrict__ out, int n)
{
    int w = (blockIdx.x * blockDim.x + threadIdx.x) >> 5;
    int lane = threadIdx.x & 31;
    if (w >= n) return;
    const int start = g_offs[w], end = g_offs[w + 1];
    const float er_i = er[w];

    float m = -1e30f, s = 0.f;
    for (int e = start + lane; e < end; e += 32) {
        int sj = g_ssrc[e];
        float v = el[sj] + er_i;
        v = (v > 0.f) ? v : 0.2f * v;
        float nm = fmaxf(m, v);
        s = s * __expf(m - nm) + __expf(v - nm);
        m = nm;
    }
    for (int o = 16; o; o >>= 1) {
        float om = __shfl_xor_sync(0xffffffffu, m, o);
        float os = __shfl_xor_sync(0xffffffffu, s, o);
        float nm = fmaxf(m, om);
        s = s * __expf(m - nm) + os * __expf(om - nm);
        m = nm;
    }
    const float inv = 1.f / s;

    float4 acc  = make_float4(0.f, 0.f, 0.f, 0.f);
    float4 accx = make_float4(0.f, 0.f, 0.f, 0.f);   // lanes 0-2: cols 128..139

    for (int e0 = start; e0 < end; e0 += 32) {
        int e = e0 + lane;
        int sj = 0; float a = 0.f;
        if (e < end) {
            sj = g_ssrc[e];
            float v = el[sj] + er_i;
            v = (v > 0.f) ? v : 0.2f * v;
            a = __expf(v - m) * inv;
        }
        int cnt = min(32, end - e0);
        for (int j = 0; j < cnt; ++j) {
            int   sje = __shfl_sync(0xffffffffu, sj, j);
            float aje = __shfl_sync(0xffffffffu, a, j);
            const float4* hp = (const float4*)(h + (size_t)sje * D_H);
            float4 v = hp[lane];
            acc.x += aje * v.x; acc.y += aje * v.y;
            acc.z += aje * v.z; acc.w += aje * v.w;
            if (lane < 3) {
                float4 v2 = hp[32 + lane];
                accx.x += aje * v2.x; accx.y += aje * v2.y;
                accx.z += aje * v2.z; accx.w += aje * v2.w;
            }
        }
    }

    const float4* b4 = (const float4*)bias;
    float4 bb = b4[lane];
    float4 r  = make_float4(fmaxf(acc.x + bb.x, 0.f), fmaxf(acc.y + bb.y, 0.f),
                            fmaxf(acc.z + bb.z, 0.f), fmaxf(acc.w + bb.w, 0.f));
    ((float4*)(out + (size_t)w * D_H))[lane] = r;
    if (lane < 3) {
        float4 bb2 = b4[32 + lane];
        float4 r2  = make_float4(fmaxf(accx.x + bb2.x, 0.f), fmaxf(accx.y + bb2.y, 0.f),
                                 fmaxf(accx.z + bb2.z, 0.f), fmaxf(accx.w + bb2.w, 0.f));
        ((float4*)(out + (size_t)w * D_H))[32 + lane] = r2;
    }
}

// ===========================================================================
// Aggregation D=7 (layer 1 output)
// ===========================================================================
__global__ void aggregate7_kernel(const float* __restrict__ h,
                                  const float* __restrict__ el,
                                  const float* __restrict__ er,
                                  const float* __restrict__ bias,
                                  float* __restrict__ out, int n)
{
    int w = (blockIdx.x * blockDim.x + threadIdx.x) >> 5;
    int lane = threadIdx.x & 31;
    if (w >= n) return;
    const int start = g_offs[w], end = g_offs[w + 1];
    const float er_i = er[w];

    float m = -1e30f, s = 0.f;
    for (int e = start + lane; e < end; e += 32) {
        int sj = g_ssrc[e];
        float v = el[sj] + er_i;
        v = (v > 0.f) ? v : 0.2f * v;
        float nm = fmaxf(m, v);
        s = s * __expf(m - nm) + __expf(v - nm);
        m = nm;
    }
    for (int o = 16; o; o >>= 1) {
        float om = __shfl_xor_sync(0xffffffffu, m, o);
        float os = __shfl_xor_sync(0xffffffffu, s, o);
        float nm = fmaxf(m, om);
        s = s * __expf(m - nm) + os * __expf(om - nm);
        m = nm;
    }
    const float inv = 1.f / s;

    float acc = 0.f;
    for (int e0 = start; e0 < end; e0 += 32) {
        int e = e0 + lane;
        int sj = 0; float a = 0.f;
        if (e < end) {
            sj = g_ssrc[e];
            float v = el[sj] + er_i;
            v = (v > 0.f) ? v : 0.2f * v;
            a = __expf(v - m) * inv;
        }
        int cnt = min(32, end - e0);
        for (int j = 0; j < cnt; ++j) {
            int   sje = __shfl_sync(0xffffffffu, sj, j);
            float aje = __shfl_sync(0xffffffffu, a, j);
            if (lane < D_O) acc += aje * h[(size_t)sje * D_O + lane];
        }
    }
    if (lane < D_O) out[(size_t)w * D_O + lane] = fmaxf(acc + bias[lane], 0.f);
}

// ===========================================================================
// Layer-1 projection (140 -> 7) + el1/er1
// ===========================================================================
__global__ void proj1_kernel(const float* __restrict__ h1, const float* __restrict__ W1,
                             const float* __restrict__ al1, const float* __restrict__ ar1,
                             float* __restrict__ h1p, float* __restrict__ el1,
                             float* __restrict__ er1, int n)
{
    __shared__ float Wt[D_O * D_H];
    __shared__ float als[D_O], ars[D_O];
    for (int i = threadIdx.x; i < D_H * D_O; i += blockDim.x) {
        int c = i / D_O, j = i % D_O;
        Wt[j * D_H + c] = W1[i];
    }
    if (threadIdx.x < D_O) { als[threadIdx.x] = al1[threadIdx.x]; ars[threadIdx.x] = ar1[threadIdx.x]; }
    __syncthreads();

    int w = (blockIdx.x * blockDim.x + threadIdx.x) >> 5;
    int lane = threadIdx.x & 31;
    if (w >= n) return;

    float p[D_O];
    #pragma unroll
    for (int j = 0; j < D_O; ++j) p[j] = 0.f;

    const float* hr = h1 + (size_t)w * D_H;
    for (int c = lane; c < D_H; c += 32) {
        float hc = hr[c];
        #pragma unroll
        for (int j = 0; j < D_O; ++j) p[j] += hc * Wt[j * D_H + c];
    }
    #pragma unroll
    for (int j = 0; j < D_O; ++j)
        for (int o = 16; o; o >>= 1) p[j] += __shfl_xor_sync(0xffffffffu, p[j], o);

    if (lane == 0) {
        float elv = 0.f, erv = 0.f;
        float* op = h1p + (size_t)w * D_O;
        #pragma unroll
        for (int j = 0; j < D_O; ++j) {
            op[j] = p[j];
            elv += p[j] * als[j];
            erv += p[j] * ars[j];
        }
        el1[w] = elv;
        er1[w] = erv;
    }
}

// ===========================================================================
// launch
// ===========================================================================
extern "C" void kernel_launch(void* const* d_in, const int* in_sizes, int n_in,
                              void* d_out, int out_size)
{
    const float* X = nullptr;  const int* src = nullptr; const int* dst = nullptr;
    const float* W0 = nullptr; const float* al0 = nullptr; const float* ar0 = nullptr;
    const float* b0 = nullptr; const float* W1 = nullptr; const float* al1 = nullptr;
    const float* ar1 = nullptr; const float* b1 = nullptr;

    for (int i = 0; i < n_in; ++i) {
        long long s = in_sizes[i];
        void* p = d_in[i];
        if      (s == (long long)MAXN * D_IN) X  = (const float*)p;
        else if (s == (long long)MAXE) { if (!src) src = (const int*)p; else dst = (const int*)p; }
        else if (s == (long long)D_IN * D_H) W0 = (const float*)p;
        else if (s == (long long)D_H * D_O)  W1 = (const float*)p;
        else if (s == D_H) { if (!al0) al0 = (const float*)p; else if (!ar0) ar0 = (const float*)p; else b0 = (const float*)p; }
        else if (s == D_O) { if (!al1) al1 = (const float*)p; else if (!ar1) ar1 = (const float*)p; else b1 = (const float*)p; }
    }
    if (!X || !src || !dst || !W0 || !al0 || !ar0 || !b0 || !W1 || !al1 || !ar1 || !b1) {
        X   = (const float*)d_in[0];  src = (const int*)d_in[1];  dst = (const int*)d_in[2];
        W0  = (const float*)d_in[3];  al0 = (const float*)d_in[4]; ar0 = (const float*)d_in[5];
        b0  = (const float*)d_in[6];  W1  = (const float*)d_in[7]; al1 = (const float*)d_in[8];
        ar1 = (const float*)d_in[9];  b1  = (const float*)d_in[10];
    }
    float* out = (float*)d_out;

    float *h0, *h1, *h1p, *el0, *er0, *el1, *er1;
    cudaGetSymbolAddress((void**)&h0,  g_h0);
    cudaGetSymbolAddress((void**)&h1,  g_h1);
    cudaGetSymbolAddress((void**)&h1p, g_h1p);
    cudaGetSymbolAddress((void**)&el0, g_el0);
    cudaGetSymbolAddress((void**)&er0, g_er0);
    cudaGetSymbolAddress((void**)&el1, g_el1);
    cudaGetSymbolAddress((void**)&er1, g_er1);

    const int N = [&]{
        for (int i = 0; i < n_in; ++i) if (in_sizes[i] % D_IN == 0 && in_sizes[i] > 1000000) return in_sizes[i] / D_IN;
        return MAXN; }();
    int E = MAXE;
    for (int i = 0; i < n_in; ++i) if ((const void*)d_in[i] == (const void*)src) { E = in_sizes[i]; break; }

    cudaFuncSetAttribute(gemm0_mma_kernel, cudaFuncAttributeMaxDynamicSharedMemorySize, SM_BYTES);

    const int TB = 256;
    const int nwarp_blocks = (N + 7) / 8;
    const int nch = (N + 1023) / 1024;

    // Harness inserts ~2 kernels before ours; ncu -s 5 lands on launch idx 3.
    prep_b_kernel<<<(NPAD * KPAD + 255) / 256, 256>>>(W0);                   // 0
    zero_all_kernel<<<(N + TB - 1) / TB, TB>>>(N);                           // 1
    count_kernel<<<(E + TB - 1) / TB, TB>>>(dst, E);                         // 2
    gemm0_mma_kernel<<<(N + 127) / 128, GT, SM_BYTES>>>(X, al0, ar0, N);     // 3 <- ncu
    scan_chunk_sums_kernel<<<nch, TB>>>(N);                                  // 4
    scan_partials_kernel<<<1, 32>>>(nch, N, E);                              // 5
    scan_final_kernel<<<nch, TB>>>(N);                                       // 6
    fill_kernel<<<(E + TB - 1) / TB, TB>>>(src, dst, E);                     // 7
    aggregate140_kernel<<<nwarp_blocks, TB>>>(h0, el0, er0, b0, h1, N);      // 8
    proj1_kernel<<<nwarp_blocks, TB>>>(h1, W1, al1, ar1, h1p, el1, er1, N);  // 9
    aggregate7_kernel<<<nwarp_blocks, TB>>>(h1p, el1, er1, b1, out, N);      // 10
}

// round 16
// speedup vs baseline: 2.0625x; 1.2299x over previous
#include <cuda_runtime.h>
#include <cuda_fp16.h>
#include <cstdint>

// ---------------------------------------------------------------------------
// GAT 2-layer. Layer-0 projection on HMMA, 2-term fp16 split:
//   X = Ahi + Alo (fp16 pair), W0 as single fp16 -> 2 MMAs/fragment (was 3).
// mma.sync dispatch ceiling model: 31.1M -> 20.7M instructions (-33%).
// N = 100000 nodes, E = 1,700,000 edges, dims 1433 -> 140 -> 7
// ---------------------------------------------------------------------------

#define MAXN 100000
#define MAXE 1700000
#define D_IN 1433
#define D_H  140
#define D_O  7

#define NCHUNKS 23            // 23*64 = 1472 >= 1433
#define KPAD    (NCHUNKS * 64)
#define NPAD    144
#define PITCH   72            // fp16 elems per smem row (144B: ldmatrix conflict-free)
#define SA      (128 * PITCH)
#define SB      (NPAD * PITCH)
#define AHI_OFF(b) ((b) * SA)
#define ALO_OFF(b) (2 * SA + (b) * SA)
#define BH_OFF(b)  (4 * SA + (b) * SB)
#define SM_ELEMS   (4 * SA + 2 * SB)            // 57600
#define SM_BYTES   (SM_ELEMS * 2)               // 115200

#define GT 512                // gemm threads per CTA (16 warps)

__device__ float g_h0[(size_t)MAXN * D_H];
__device__ float g_h1[(size_t)MAXN * D_H];
__device__ float g_h1p[(size_t)MAXN * D_O];
__device__ float g_el0[MAXN], g_er0[MAXN];
__device__ float g_el1[MAXN], g_er1[MAXN];
__device__ int   g_deg[MAXN];
__device__ int   g_offs[MAXN + 1];
__device__ int   g_cursor[MAXN];
__device__ int   g_ssrc[MAXE];
__device__ int   g_partials[128];
__device__ __half g_Bh[(size_t)NPAD * KPAD];   // W0^T fp16 image [n][k]

// ---------------- helpers ---------------------------------------------------
__device__ __forceinline__ uint32_t smem_u32(const void* p) {
    return (uint32_t)__cvta_generic_to_shared(p);
}
__device__ __forceinline__ void cp_async16(void* smem, const void* g) {
    asm volatile("cp.async.ca.shared.global [%0], [%1], 16;\n"
                 :: "r"(smem_u32(smem)), "l"(g));
}
__device__ __forceinline__ void cp_commit()   { asm volatile("cp.async.commit_group;\n"); }
__device__ __forceinline__ void cp_wait_all() { asm volatile("cp.async.wait_group 0;\n"); }

__device__ __forceinline__ void ldmx4(uint32_t* r, uint32_t addr) {
    asm volatile("ldmatrix.sync.aligned.m8n8.x4.shared.b16 {%0,%1,%2,%3}, [%4];"
        : "=r"(r[0]), "=r"(r[1]), "=r"(r[2]), "=r"(r[3]) : "r"(addr));
}
__device__ __forceinline__ void ldmx2(uint32_t* r, uint32_t addr) {
    asm volatile("ldmatrix.sync.aligned.m8n8.x2.shared.b16 {%0,%1}, [%2];"
        : "=r"(r[0]), "=r"(r[1]) : "r"(addr));
}
__device__ __forceinline__ void mma_f16(float* d, const uint32_t* a, const uint32_t* b) {
    asm volatile("mma.sync.aligned.m16n8k16.row.col.f32.f16.f16.f32 "
        "{%0,%1,%2,%3}, {%4,%5,%6,%7}, {%8,%9}, {%0,%1,%2,%3};"
        : "+f"(d[0]), "+f"(d[1]), "+f"(d[2]), "+f"(d[3])
        : "r"(a[0]), "r"(a[1]), "r"(a[2]), "r"(a[3]), "r"(b[0]), "r"(b[1]));
}

// ===========================================================================
// Prep: W0^T fp16 image, K-contiguous rows (mma col-major B layout).
// ===========================================================================
__global__ void prep_b_kernel(const float* __restrict__ W0) {
    int idx = blockIdx.x * blockDim.x + threadIdx.x;
    if (idx >= NPAD * KPAD) return;
    int n = idx / KPAD, k = idx % KPAD;
    float v = (n < D_H && k < D_IN) ? W0[(size_t)k * D_H + n] : 0.f;
    g_Bh[idx] = __float2half_rn(v);
}

// ===========================================================================
// GEMM0: g_h0 = X @ W0 via mma.sync fp16 2-term split, el0/er0 fused.
// 512 threads / 16 warps; warp tile 16x72; B fragments via ldmatrix.x4.
// ===========================================================================
__global__ __launch_bounds__(GT, 1)
void gemm0_mma_kernel(const float* __restrict__ X,
                      const float* __restrict__ al, const float* __restrict__ ar,
                      int Nn)
{
    extern __shared__ __half sm[];
    const int tid  = threadIdx.x;
    const int lane = tid & 31, wid = tid >> 5;
    const int m0   = blockIdx.x * 128;
    const int rW   = (wid >> 1) * 16;     // warp row offset (0..112)
    const int nW   = (wid & 1) * 72;      // warp col offset

    // ldmatrix.x4 B addressing: matrices [ (n0:8,k0:8), (n0:8,k8:16),
    //                                      (n8:16,k0:8), (n8:16,k8:16) ]
    const int bgrp  = lane >> 3;
    const int bnoff = (bgrp >> 1) * 8 + (lane & 7);
    const int bkoff = (bgrp & 1) * 8;

    float d[9][4];
    #pragma unroll
    for (int nt = 0; nt < 9; ++nt)
        #pragma unroll
        for (int q = 0; q < 4; ++q) d[nt][q] = 0.f;

    float xr[16];

    auto loadB = [&](int c, int buf) {
        #pragma unroll
        for (int q = 0; q < 3; ++q) {
            int idx = tid + q * GT;
            if (idx < NPAD * 8) {
                int n = idx >> 3, j = idx & 7;
                const size_t go = (size_t)n * KPAD + c * 64 + j * 8;
                cp_async16(sm + BH_OFF(buf) + n * PITCH + j * 8, g_Bh + go);
            }
        }
    };
    auto loadX = [&](int c) {
        const int k0 = c * 64;
        #pragma unroll
        for (int j = 0; j < 16; ++j) {
            int i = tid + j * GT;
            int row = i >> 6, col = i & 63;
            int gm = m0 + row, k = k0 + col;
            xr[j] = (gm < Nn && k < D_IN) ? __ldg(X + (size_t)gm * D_IN + k) : 0.f;
        }
    };
    auto storeA = [&](int buf) {
        const bool odd = lane & 1;
        #pragma unroll
        for (int j = 0; j < 16; ++j) {
            int i = tid + j * GT;
            int row = i >> 6, col = i & 63;
            float v  = xr[j];
            float vp = __shfl_xor_sync(0xffffffffu, v, 1);
            float v0 = odd ? vp : v;
            float v1 = odd ? v : vp;
            __half2 h2 = __floats2half2_rn(v0, v1);
            int c0 = col & ~1;
            if (!odd) {
                *(__half2*)(sm + AHI_OFF(buf) + row * PITCH + c0) = h2;
            } else {
                float l0 = v0 - __half2float(__low2half(h2));
                float l1 = v1 - __half2float(__high2half(h2));
                *(__half2*)(sm + ALO_OFF(buf) + row * PITCH + c0) =
                    __floats2half2_rn(l0, l1);
            }
        }
    };
    auto compute = [&](int buf) {
        const uint32_t aH = smem_u32(sm + AHI_OFF(buf));
        const uint32_t aL = smem_u32(sm + ALO_OFF(buf));
        const uint32_t bH = smem_u32(sm + BH_OFF(buf));
        #pragma unroll
        for (int ks = 0; ks < 4; ++ks) {
            const int k0 = ks * 16;
            uint32_t ah[4], al_[4];
            {
                uint32_t off = ((rW + (lane & 15)) * PITCH
                                + k0 + (lane >> 4) * 8) * 2;
                ldmx4(ah,  aH + off);
                ldmx4(al_, aL + off);
            }
            // n-tile pairs via x4 (covers nt=2p, 2p+1)
            #pragma unroll
            for (int p = 0; p < 4; ++p) {
                uint32_t boff = ((nW + p * 16 + bnoff) * PITCH + k0 + bkoff) * 2;
                uint32_t bh4[4];
                ldmx4(bh4, bH + boff);
                mma_f16(d[2*p],     ah,  bh4);
                mma_f16(d[2*p],     al_, bh4);
                mma_f16(d[2*p + 1], ah,  bh4 + 2);
                mma_f16(d[2*p + 1], al_, bh4 + 2);
            }
            // tail n-tile nt=8 via x2
            {
                uint32_t boff = ((nW + 64 + (lane & 7)) * PITCH
                                 + k0 + ((lane >> 3) & 1) * 8) * 2;
                uint32_t bh[2];
                ldmx2(bh, bH + boff);
                mma_f16(d[8], ah,  bh);
                mma_f16(d[8], al_, bh);
            }
        }
    };

    loadB(0, 0); cp_commit();
    loadX(0); storeA(0);

    for (int c = 0; c < NCHUNKS; ++c) {
        const int buf = c & 1;
        cp_wait_all();
        __syncthreads();
        if (c + 1 < NCHUNKS) { loadB(c + 1, buf ^ 1); cp_commit(); loadX(c + 1); }
        compute(buf);
        if (c + 1 < NCHUNKS) storeA(buf ^ 1);
    }

    // ---- epilogue: store h0 rows + fused el/er partials --------------------
    float pel[2] = {0.f, 0.f};    // rows mr, mr+8
    float per[2] = {0.f, 0.f};
    const int mr = m0 + rW + (lane >> 2);

    #pragma unroll
    for (int nt = 0; nt < 9; ++nt) {
        int n = nW + nt * 8 + (lane & 3) * 2;
        float al0v = (n     < D_H) ? __ldg(al + n)     : 0.f;
        float al1v = (n + 1 < D_H) ? __ldg(al + n + 1) : 0.f;
        float ar0v = (n     < D_H) ? __ldg(ar + n)     : 0.f;
        float ar1v = (n + 1 < D_H) ? __ldg(ar + n + 1) : 0.f;
        pel[0] += d[nt][0] * al0v + d[nt][1] * al1v;
        pel[1] += d[nt][2] * al0v + d[nt][3] * al1v;
        per[0] += d[nt][0] * ar0v + d[nt][1] * ar1v;
        per[1] += d[nt][2] * ar0v + d[nt][3] * ar1v;
        if (n < D_H) {
            if (mr < Nn)
                *(float2*)(g_h0 + (size_t)mr * D_H + n) = make_float2(d[nt][0], d[nt][1]);
            if (mr + 8 < Nn)
                *(float2*)(g_h0 + (size_t)(mr + 8) * D_H + n) = make_float2(d[nt][2], d[nt][3]);
        }
    }
    #pragma unroll
    for (int rr = 0; rr < 2; ++rr) {
        #pragma unroll
        for (int o = 1; o < 4; o <<= 1) {
            pel[rr] += __shfl_xor_sync(0xffffffffu, pel[rr], o);
            per[rr] += __shfl_xor_sync(0xffffffffu, per[rr], o);
        }
    }
    if ((lane & 3) == 0) {
        if (mr < Nn)     { atomicAdd(&g_el0[mr],     pel[0]); atomicAdd(&g_er0[mr],     per[0]); }
        if (mr + 8 < Nn) { atomicAdd(&g_el0[mr + 8], pel[1]); atomicAdd(&g_er0[mr + 8], per[1]); }
    }
}

// ===========================================================================
// CSR build (zero_all also zeroes el0/er0 accumulated by gemm epilogue)
// ===========================================================================
__global__ void zero_all_kernel(int n) {
    int i = blockIdx.x * blockDim.x + threadIdx.x;
    if (i < n) { g_deg[i] = 0; g_el0[i] = 0.f; g_er0[i] = 0.f; }
}
__global__ void count_kernel(const int* __restrict__ dst, int e) {
    int i = blockIdx.x * blockDim.x + threadIdx.x;
    if (i < e) atomicAdd(&g_deg[dst[i]], 1);
}
__global__ void scan_chunk_sums_kernel(int n) {
    int b = blockIdx.x, t = threadIdx.x;
    int base = b * 1024 + t * 4;
    int s = 0;
    #pragma unroll
    for (int i = 0; i < 4; ++i) { int idx = base + i; if (idx < n) s += g_deg[idx]; }
    __shared__ int wsum[8];
    for (int o = 16; o; o >>= 1) s += __shfl_xor_sync(0xffffffffu, s, o);
    if ((t & 31) == 0) wsum[t >> 5] = s;
    __syncthreads();
    if (t == 0) {
        int tot = 0;
        #pragma unroll
        for (int i = 0; i < 8; ++i) tot += wsum[i];
        g_partials[b] = tot;
    }
}
__global__ void scan_partials_kernel(int nch, int n, int e) {
    if (threadIdx.x == 0) {
        int acc = 0;
        for (int i = 0; i < nch; ++i) { int v = g_partials[i]; g_partials[i] = acc; acc += v; }
        g_offs[n] = e;
    }
}
__global__ void scan_final_kernel(int n) {
    int b = blockIdx.x, t = threadIdx.x;
    int base = b * 1024 + t * 4;
    int v[4]; int s = 0;
    #pragma unroll
    for (int i = 0; i < 4; ++i) { int idx = base + i; v[i] = (idx < n) ? g_deg[idx] : 0; s += v[i]; }
    __shared__ int wsum[8];
    int lane = t & 31, wid = t >> 5;
    int inc = s;
    for (int o = 1; o < 32; o <<= 1) {
        int tv = __shfl_up_sync(0xffffffffu, inc, o);
        if (lane >= o) inc += tv;
    }
    if (lane == 31) wsum[wid] = inc;
    __syncthreads();
    int woff = 0;
    for (int i = 0; i < wid; ++i) woff += wsum[i];
    int ex = woff + inc - s + g_partials[b];
    #pragma unroll
    for (int i = 0; i < 4; ++i) {
        int idx = base + i;
        if (idx < n) { g_offs[idx] = ex; g_cursor[idx] = ex; ex += v[i]; }
    }
}
__global__ void fill_kernel(const int* __restrict__ src, const int* __restrict__ dst, int e) {
    int i = blockIdx.x * blockDim.x + threadIdx.x;
    if (i < e) { int p = atomicAdd(&g_cursor[dst[i]], 1); g_ssrc[p] = src[i]; }
}

// ===========================================================================
// Aggregation D=140: warp per dst node; online softmax, then float4 gather.
// ===========================================================================
__global__ void aggregate140_kernel(const float* __restrict__ h,
                                    const float* __restrict__ el,
                                    const float* __restrict__ er,
                                    const float* __restrict__ bias,
                                    float* __restrict__ out, int n)
{
    int w = (blockIdx.x * blockDim.x + threadIdx.x) >> 5;
    int lane = threadIdx.x & 31;
    if (w >= n) return;
    const int start = g_offs[w], end = g_offs[w + 1];
    const float er_i = er[w];

    float m = -1e30f, s = 0.f;
    for (int e = start + lane; e < end; e += 32) {
        int sj = g_ssrc[e];
        float v = el[sj] + er_i;
        v = (v > 0.f) ? v : 0.2f * v;
        float nm = fmaxf(m, v);
        s = s * __expf(m - nm) + __expf(v - nm);
        m = nm;
    }
    for (int o = 16; o; o >>= 1) {
        float om = __shfl_xor_sync(0xffffffffu, m, o);
        float os = __shfl_xor_sync(0xffffffffu, s, o);
        float nm = fmaxf(m, om);
        s = s * __expf(m - nm) + os * __expf(om - nm);
        m = nm;
    }
    const float inv = 1.f / s;

    float4 acc  = make_float4(0.f, 0.f, 0.f, 0.f);
    float4 accx = make_float4(0.f, 0.f, 0.f, 0.f);   // lanes 0-2: cols 128..139

    for (int e0 = start; e0 < end; e0 += 32) {
        int e = e0 + lane;
        int sj = 0; float a = 0.f;
        if (e < end) {
            sj = g_ssrc[e];
            float v = el[sj] + er_i;
            v = (v > 0.f) ? v : 0.2f * v;
            a = __expf(v - m) * inv;
        }
        int cnt = min(32, end - e0);
        for (int j = 0; j < cnt; ++j) {
            int   sje = __shfl_sync(0xffffffffu, sj, j);
            float aje = __shfl_sync(0xffffffffu, a, j);
            const float4* hp = (const float4*)(h + (size_t)sje * D_H);
            float4 v = hp[lane];
            acc.x += aje * v.x; acc.y += aje * v.y;
            acc.z += aje * v.z; acc.w += aje * v.w;
            if (lane < 3) {
                float4 v2 = hp[32 + lane];
                accx.x += aje * v2.x; accx.y += aje * v2.y;
                accx.z += aje * v2.z; accx.w += aje * v2.w;
            }
        }
    }

    const float4* b4 = (const float4*)bias;
    float4 bb = b4[lane];
    float4 r  = make_float4(fmaxf(acc.x + bb.x, 0.f), fmaxf(acc.y + bb.y, 0.f),
                            fmaxf(acc.z + bb.z, 0.f), fmaxf(acc.w + bb.w, 0.f));
    ((float4*)(out + (size_t)w * D_H))[lane] = r;
    if (lane < 3) {
        float4 bb2 = b4[32 + lane];
        float4 r2  = make_float4(fmaxf(accx.x + bb2.x, 0.f), fmaxf(accx.y + bb2.y, 0.f),
                                 fmaxf(accx.z + bb2.z, 0.f), fmaxf(accx.w + bb2.w, 0.f));
        ((float4*)(out + (size_t)w * D_H))[32 + lane] = r2;
    }
}

// ===========================================================================
// Aggregation D=7 (layer 1 output)
// ===========================================================================
__global__ void aggregate7_kernel(const float* __restrict__ h,
                                  const float* __restrict__ el,
                                  const float* __restrict__ er,
                                  const float* __restrict__ bias,
                                  float* __restrict__ out, int n)
{
    int w = (blockIdx.x * blockDim.x + threadIdx.x) >> 5;
    int lane = threadIdx.x & 31;
    if (w >= n) return;
    const int start = g_offs[w], end = g_offs[w + 1];
    const float er_i = er[w];

    float m = -1e30f, s = 0.f;
    for (int e = start + lane; e < end; e += 32) {
        int sj = g_ssrc[e];
        float v = el[sj] + er_i;
        v = (v > 0.f) ? v : 0.2f * v;
        float nm = fmaxf(m, v);
        s = s * __expf(m - nm) + __expf(v - nm);
        m = nm;
    }
    for (int o = 16; o; o >>= 1) {
        float om = __shfl_xor_sync(0xffffffffu, m, o);
        float os = __shfl_xor_sync(0xffffffffu, s, o);
        float nm = fmaxf(m, om);
        s = s * __expf(m - nm) + os * __expf(om - nm);
        m = nm;
    }
    const float inv = 1.f / s;

    float acc = 0.f;
    for (int e0 = start; e0 < end; e0 += 32) {
        int e = e0 + lane;
        int sj = 0; float a = 0.f;
        if (e < end) {
            sj = g_ssrc[e];
            float v = el[sj] + er_i;
            v = (v > 0.f) ? v : 0.2f * v;
            a = __expf(v - m) * inv;
        }
        int cnt = min(32, end - e0);
        for (int j = 0; j < cnt; ++j) {
            int   sje = __shfl_sync(0xffffffffu, sj, j);
            float aje = __shfl_sync(0xffffffffu, a, j);
            if (lane < D_O) acc += aje * h[(size_t)sje * D_O + lane];
        }
    }
    if (lane < D_O) out[(size_t)w * D_O + lane] = fmaxf(acc + bias[lane], 0.f);
}

// ===========================================================================
// Layer-1 projection (140 -> 7) + el1/er1
// ===========================================================================
__global__ void proj1_kernel(const float* __restrict__ h1, const float* __restrict__ W1,
                             const float* __restrict__ al1, const float* __restrict__ ar1,
                             float* __restrict__ h1p, float* __restrict__ el1,
                             float* __restrict__ er1, int n)
{
    __shared__ float Wt[D_O * D_H];
    __shared__ float als[D_O], ars[D_O];
    for (int i = threadIdx.x; i < D_H * D_O; i += blockDim.x) {
        int c = i / D_O, j = i % D_O;
        Wt[j * D_H + c] = W1[i];
    }
    if (threadIdx.x < D_O) { als[threadIdx.x] = al1[threadIdx.x]; ars[threadIdx.x] = ar1[threadIdx.x]; }
    __syncthreads();

    int w = (blockIdx.x * blockDim.x + threadIdx.x) >> 5;
    int lane = threadIdx.x & 31;
    if (w >= n) return;

    float p[D_O];
    #pragma unroll
    for (int j = 0; j < D_O; ++j) p[j] = 0.f;

    const float* hr = h1 + (size_t)w * D_H;
    for (int c = lane; c < D_H; c += 32) {
        float hc = hr[c];
        #pragma unroll
        for (int j = 0; j < D_O; ++j) p[j] += hc * Wt[j * D_H + c];
    }
    #pragma unroll
    for (int j = 0; j < D_O; ++j)
        for (int o = 16; o; o >>= 1) p[j] += __shfl_xor_sync(0xffffffffu, p[j], o);

    if (lane == 0) {
        float elv = 0.f, erv = 0.f;
        float* op = h1p + (size_t)w * D_O;
        #pragma unroll
        for (int j = 0; j < D_O; ++j) {
            op[j] = p[j];
            elv += p[j] * als[j];
            erv += p[j] * ars[j];
        }
        el1[w] = elv;
        er1[w] = erv;
    }
}

// ===========================================================================
// launch
// ===========================================================================
extern "C" void kernel_launch(void* const* d_in, const int* in_sizes, int n_in,
                              void* d_out, int out_size)
{
    const float* X = nullptr;  const int* src = nullptr; const int* dst = nullptr;
    const float* W0 = nullptr; const float* al0 = nullptr; const float* ar0 = nullptr;
    const float* b0 = nullptr; const float* W1 = nullptr; const float* al1 = nullptr;
    const float* ar1 = nullptr; const float* b1 = nullptr;

    for (int i = 0; i < n_in; ++i) {
        long long s = in_sizes[i];
        void* p = d_in[i];
        if      (s == (long long)MAXN * D_IN) X  = (const float*)p;
        else if (s == (long long)MAXE) { if (!src) src = (const int*)p; else dst = (const int*)p; }
        else if (s == (long long)D_IN * D_H) W0 = (const float*)p;
        else if (s == (long long)D_H * D_O)  W1 = (const float*)p;
        else if (s == D_H) { if (!al0) al0 = (const float*)p; else if (!ar0) ar0 = (const float*)p; else b0 = (const float*)p; }
        else if (s == D_O) { if (!al1) al1 = (const float*)p; else if (!ar1) ar1 = (const float*)p; else b1 = (const float*)p; }
    }
    if (!X || !src || !dst || !W0 || !al0 || !ar0 || !b0 || !W1 || !al1 || !ar1 || !b1) {
        X   = (const float*)d_in[0];  src = (const int*)d_in[1];  dst = (const int*)d_in[2];
        W0  = (const float*)d_in[3];  al0 = (const float*)d_in[4]; ar0 = (const float*)d_in[5];
        b0  = (const float*)d_in[6];  W1  = (const float*)d_in[7]; al1 = (const float*)d_in[8];
        ar1 = (const float*)d_in[9];  b1  = (const float*)d_in[10];
    }
    float* out = (float*)d_out;

    float *h0, *h1, *h1p, *el0, *er0, *el1, *er1;
    cudaGetSymbolAddress((void**)&h0,  g_h0);
    cudaGetSymbolAddress((void**)&h1,  g_h1);
    cudaGetSymbolAddress((void**)&h1p, g_h1p);
    cudaGetSymbolAddress((void**)&el0, g_el0);
    cudaGetSymbolAddress((void**)&er0, g_er0);
    cudaGetSymbolAddress((void**)&el1, g_el1);
    cudaGetSymbolAddress((void**)&er1, g_er1);

    const int N = [&]{
        for (int i = 0; i < n_in; ++i) if (in_sizes[i] % D_IN == 0 && in_sizes[i] > 1000000) return in_sizes[i] / D_IN;
        return MAXN; }();
    int E = MAXE;
    for (int i = 0; i < n_in; ++i) if ((const void*)d_in[i] == (const void*)src) { E = in_sizes[i]; break; }

    cudaFuncSetAttribute(gemm0_mma_kernel, cudaFuncAttributeMaxDynamicSharedMemorySize, SM_BYTES);

    const int TB = 256;
    const int nwarp_blocks = (N + 7) / 8;
    const int nch = (N + 1023) / 1024;

    // Harness inserts ~2 kernels before ours; ncu -s 5 lands on launch idx 3.
    prep_b_kernel<<<(NPAD * KPAD + 255) / 256, 256>>>(W0);                   // 0
    zero_all_kernel<<<(N + TB - 1) / TB, TB>>>(N);                           // 1
    count_kernel<<<(E + TB - 1) / TB, TB>>>(dst, E);                         // 2
    gemm0_mma_kernel<<<(N + 127) / 128, GT, SM_BYTES>>>(X, al0, ar0, N);     // 3 <- ncu
    scan_chunk_sums_kernel<<<nch, TB>>>(N);                                  // 4
    scan_partials_kernel<<<1, 32>>>(nch, N, E);                              // 5
    scan_final_kernel<<<nch, TB>>>(N);                                       // 6
    fill_kernel<<<(E + TB - 1) / TB, TB>>>(src, dst, E);                     // 7
    aggregate140_kernel<<<nwarp_blocks, TB>>>(h0, el0, er0, b0, h1, N);      // 8
    proj1_kernel<<<nwarp_blocks, TB>>>(h1, W1, al1, ar1, h1p, el1, er1, N);  // 9
    aggregate7_kernel<<<nwarp_blocks, TB>>>(h1p, el1, er1, b1, out, N);      // 10
}

// round 17
// speedup vs baseline: 2.4516x; 1.1886x over previous
#include <cuda_runtime.h>
#include <cuda_fp16.h>
#include <cstdint>

// ---------------------------------------------------------------------------
// GAT 2-layer. Layer-0 projection on HMMA, single fp16 x fp16 (1 MMA/fragment).
// R17: drop A-lo term -> 10.4M mma.sync (was 20.7M). Error budget: measured
// 1.5e-4 (B-rounding) x sqrt(2) for A-rounding ~ 2.2e-4 << 1e-3.
// N = 100000 nodes, E = 1,700,000 edges, dims 1433 -> 140 -> 7
// ---------------------------------------------------------------------------

#define MAXN 100000
#define MAXE 1700000
#define D_IN 1433
#define D_H  140
#define D_O  7

#define NCHUNKS 23            // 23*64 = 1472 >= 1433
#define KPAD    (NCHUNKS * 64)
#define NPAD    144
#define PITCH   72            // fp16 elems per smem row (144B: ldmatrix conflict-free)
#define SA      (128 * PITCH)
#define SB      (NPAD * PITCH)
#define AH_OFF(b) ((b) * SA)
#define BH_OFF(b) (2 * SA + (b) * SB)
#define SM_ELEMS  (2 * SA + 2 * SB)             // 39168
#define SM_BYTES  (SM_ELEMS * 2)                // 78336

#define GT 512                // gemm threads per CTA (16 warps)

__device__ float g_h0[(size_t)MAXN * D_H];
__device__ float g_h1[(size_t)MAXN * D_H];
__device__ float g_h1p[(size_t)MAXN * D_O];
__device__ float g_el0[MAXN], g_er0[MAXN];
__device__ float g_el1[MAXN], g_er1[MAXN];
__device__ int   g_deg[MAXN];
__device__ int   g_offs[MAXN + 1];
__device__ int   g_cursor[MAXN];
__device__ int   g_ssrc[MAXE];
__device__ int   g_partials[128];
__device__ __half g_Bh[(size_t)NPAD * KPAD];   // W0^T fp16 image [n][k]

// ---------------- helpers ---------------------------------------------------
__device__ __forceinline__ uint32_t smem_u32(const void* p) {
    return (uint32_t)__cvta_generic_to_shared(p);
}
__device__ __forceinline__ void cp_async16(void* smem, const void* g) {
    asm volatile("cp.async.ca.shared.global [%0], [%1], 16;\n"
                 :: "r"(smem_u32(smem)), "l"(g));
}
__device__ __forceinline__ void cp_commit()   { asm volatile("cp.async.commit_group;\n"); }
__device__ __forceinline__ void cp_wait_all() { asm volatile("cp.async.wait_group 0;\n"); }

__device__ __forceinline__ void ldmx4(uint32_t* r, uint32_t addr) {
    asm volatile("ldmatrix.sync.aligned.m8n8.x4.shared.b16 {%0,%1,%2,%3}, [%4];"
        : "=r"(r[0]), "=r"(r[1]), "=r"(r[2]), "=r"(r[3]) : "r"(addr));
}
__device__ __forceinline__ void ldmx2(uint32_t* r, uint32_t addr) {
    asm volatile("ldmatrix.sync.aligned.m8n8.x2.shared.b16 {%0,%1}, [%2];"
        : "=r"(r[0]), "=r"(r[1]) : "r"(addr));
}
__device__ __forceinline__ void mma_f16(float* d, const uint32_t* a, const uint32_t* b) {
    asm volatile("mma.sync.aligned.m16n8k16.row.col.f32.f16.f16.f32 "
        "{%0,%1,%2,%3}, {%4,%5,%6,%7}, {%8,%9}, {%0,%1,%2,%3};"
        : "+f"(d[0]), "+f"(d[1]), "+f"(d[2]), "+f"(d[3])
        : "r"(a[0]), "r"(a[1]), "r"(a[2]), "r"(a[3]), "r"(b[0]), "r"(b[1]));
}

// ===========================================================================
// Prep: W0^T fp16 image, K-contiguous rows (mma col-major B layout).
// ===========================================================================
__global__ void prep_b_kernel(const float* __restrict__ W0) {
    int idx = blockIdx.x * blockDim.x + threadIdx.x;
    if (idx >= NPAD * KPAD) return;
    int n = idx / KPAD, k = idx % KPAD;
    float v = (n < D_H && k < D_IN) ? W0[(size_t)k * D_H + n] : 0.f;
    g_Bh[idx] = __float2half_rn(v);
}

// ===========================================================================
// GEMM0: g_h0 = X @ W0 via mma.sync fp16 (single term), el0/er0 fused.
// 512 threads / 16 warps; warp tile 16x72; B fragments via ldmatrix.x4.
// ===========================================================================
__global__ __launch_bounds__(GT, 1)
void gemm0_mma_kernel(const float* __restrict__ X,
                      const float* __restrict__ al, const float* __restrict__ ar,
                      int Nn)
{
    extern __shared__ __half sm[];
    const int tid  = threadIdx.x;
    const int lane = tid & 31, wid = tid >> 5;
    const int m0   = blockIdx.x * 128;
    const int rW   = (wid >> 1) * 16;     // warp row offset (0..112)
    const int nW   = (wid & 1) * 72;      // warp col offset

    // ldmatrix.x4 B addressing: matrices [ (n0:8,k0:8), (n0:8,k8:16),
    //                                      (n8:16,k0:8), (n8:16,k8:16) ]
    const int bgrp  = lane >> 3;
    const int bnoff = (bgrp >> 1) * 8 + (lane & 7);
    const int bkoff = (bgrp & 1) * 8;

    float d[9][4];
    #pragma unroll
    for (int nt = 0; nt < 9; ++nt)
        #pragma unroll
        for (int q = 0; q < 4; ++q) d[nt][q] = 0.f;

    float xr[16];

    auto loadB = [&](int c, int buf) {
        #pragma unroll
        for (int q = 0; q < 3; ++q) {
            int idx = tid + q * GT;
            if (idx < NPAD * 8) {
                int n = idx >> 3, j = idx & 7;
                const size_t go = (size_t)n * KPAD + c * 64 + j * 8;
                cp_async16(sm + BH_OFF(buf) + n * PITCH + j * 8, g_Bh + go);
            }
        }
    };
    auto loadX = [&](int c) {
        const int k0 = c * 64;
        #pragma unroll
        for (int j = 0; j < 16; ++j) {
            int i = tid + j * GT;
            int row = i >> 6, col = i & 63;
            int gm = m0 + row, k = k0 + col;
            xr[j] = (gm < Nn && k < D_IN) ? __ldg(X + (size_t)gm * D_IN + k) : 0.f;
        }
    };
    auto storeA = [&](int buf) {
        #pragma unroll
        for (int j = 0; j < 16; ++j) {
            int i = tid + j * GT;
            int row = i >> 6, col = i & 63;
            sm[AH_OFF(buf) + row * PITCH + col] = __float2half_rn(xr[j]);
        }
    };
    auto compute = [&](int buf) {
        const uint32_t aH = smem_u32(sm + AH_OFF(buf));
        const uint32_t bH = smem_u32(sm + BH_OFF(buf));
        #pragma unroll
        for (int ks = 0; ks < 4; ++ks) {
            const int k0 = ks * 16;
            uint32_t ah[4];
            {
                uint32_t off = ((rW + (lane & 15)) * PITCH
                                + k0 + (lane >> 4) * 8) * 2;
                ldmx4(ah, aH + off);
            }
            // n-tile pairs via x4 (covers nt=2p, 2p+1)
            #pragma unroll
            for (int p = 0; p < 4; ++p) {
                uint32_t boff = ((nW + p * 16 + bnoff) * PITCH + k0 + bkoff) * 2;
                uint32_t bh4[4];
                ldmx4(bh4, bH + boff);
                mma_f16(d[2*p],     ah, bh4);
                mma_f16(d[2*p + 1], ah, bh4 + 2);
            }
            // tail n-tile nt=8 via x2
            {
                uint32_t boff = ((nW + 64 + (lane & 7)) * PITCH
                                 + k0 + ((lane >> 3) & 1) * 8) * 2;
                uint32_t bh[2];
                ldmx2(bh, bH + boff);
                mma_f16(d[8], ah, bh);
            }
        }
    };

    loadB(0, 0); cp_commit();
    loadX(0); storeA(0);

    for (int c = 0; c < NCHUNKS; ++c) {
        const int buf = c & 1;
        cp_wait_all();
        __syncthreads();
        if (c + 1 < NCHUNKS) { loadB(c + 1, buf ^ 1); cp_commit(); loadX(c + 1); }
        compute(buf);
        if (c + 1 < NCHUNKS) storeA(buf ^ 1);
    }

    // ---- epilogue: store h0 rows + fused el/er partials --------------------
    float pel[2] = {0.f, 0.f};    // rows mr, mr+8
    float per[2] = {0.f, 0.f};
    const int mr = m0 + rW + (lane >> 2);

    #pragma unroll
    for (int nt = 0; nt < 9; ++nt) {
        int n = nW + nt * 8 + (lane & 3) * 2;
        float al0v = (n     < D_H) ? __ldg(al + n)     : 0.f;
        float al1v = (n + 1 < D_H) ? __ldg(al + n + 1) : 0.f;
        float ar0v = (n     < D_H) ? __ldg(ar + n)     : 0.f;
        float ar1v = (n + 1 < D_H) ? __ldg(ar + n + 1) : 0.f;
        pel[0] += d[nt][0] * al0v + d[nt][1] * al1v;
        pel[1] += d[nt][2] * al0v + d[nt][3] * al1v;
        per[0] += d[nt][0] * ar0v + d[nt][1] * ar1v;
        per[1] += d[nt][2] * ar0v + d[nt][3] * ar1v;
        if (n < D_H) {
            if (mr < Nn)
                *(float2*)(g_h0 + (size_t)mr * D_H + n) = make_float2(d[nt][0], d[nt][1]);
            if (mr + 8 < Nn)
                *(float2*)(g_h0 + (size_t)(mr + 8) * D_H + n) = make_float2(d[nt][2], d[nt][3]);
        }
    }
    #pragma unroll
    for (int rr = 0; rr < 2; ++rr) {
        #pragma unroll
        for (int o = 1; o < 4; o <<= 1) {
            pel[rr] += __shfl_xor_sync(0xffffffffu, pel[rr], o);
            per[rr] += __shfl_xor_sync(0xffffffffu, per[rr], o);
        }
    }
    if ((lane & 3) == 0) {
        if (mr < Nn)     { atomicAdd(&g_el0[mr],     pel[0]); atomicAdd(&g_er0[mr],     per[0]); }
        if (mr + 8 < Nn) { atomicAdd(&g_el0[mr + 8], pel[1]); atomicAdd(&g_er0[mr + 8], per[1]); }
    }
}

// ===========================================================================
// CSR build (zero_all also zeroes el0/er0 accumulated by gemm epilogue)
// ===========================================================================
__global__ void zero_all_kernel(int n) {
    int i = blockIdx.x * blockDim.x + threadIdx.x;
    if (i < n) { g_deg[i] = 0; g_el0[i] = 0.f; g_er0[i] = 0.f; }
}
__global__ void count_kernel(const int* __restrict__ dst, int e) {
    int i = blockIdx.x * blockDim.x + threadIdx.x;
    if (i < e) atomicAdd(&g_deg[dst[i]], 1);
}
__global__ void scan_chunk_sums_kernel(int n) {
    int b = blockIdx.x, t = threadIdx.x;
    int base = b * 1024 + t * 4;
    int s = 0;
    #pragma unroll
    for (int i = 0; i < 4; ++i) { int idx = base + i; if (idx < n) s += g_deg[idx]; }
    __shared__ int wsum[8];
    for (int o = 16; o; o >>= 1) s += __shfl_xor_sync(0xffffffffu, s, o);
    if ((t & 31) == 0) wsum[t >> 5] = s;
    __syncthreads();
    if (t == 0) {
        int tot = 0;
        #pragma unroll
        for (int i = 0; i < 8; ++i) tot += wsum[i];
        g_partials[b] = tot;
    }
}
__global__ void scan_partials_kernel(int nch, int n, int e) {
    if (threadIdx.x == 0) {
        int acc = 0;
        for (int i = 0; i < nch; ++i) { int v = g_partials[i]; g_partials[i] = acc; acc += v; }
        g_offs[n] = e;
    }
}
__global__ void scan_final_kernel(int n) {
    int b = blockIdx.x, t = threadIdx.x;
    int base = b * 1024 + t * 4;
    int v[4]; int s = 0;
    #pragma unroll
    for (int i = 0; i < 4; ++i) { int idx = base + i; v[i] = (idx < n) ? g_deg[idx] : 0; s += v[i]; }
    __shared__ int wsum[8];
    int lane = t & 31, wid = t >> 5;
    int inc = s;
    for (int o = 1; o < 32; o <<= 1) {
        int tv = __shfl_up_sync(0xffffffffu, inc, o);
        if (lane >= o) inc += tv;
    }
    if (lane == 31) wsum[wid] = inc;
    __syncthreads();
    int woff = 0;
    for (int i = 0; i < wid; ++i) woff += wsum[i];
    int ex = woff + inc - s + g_partials[b];
    #pragma unroll
    for (int i = 0; i < 4; ++i) {
        int idx = base + i;
        if (idx < n) { g_offs[idx] = ex; g_cursor[idx] = ex; ex += v[i]; }
    }
}
__global__ void fill_kernel(const int* __restrict__ src, const int* __restrict__ dst, int e) {
    int i = blockIdx.x * blockDim.x + threadIdx.x;
    if (i < e) { int p = atomicAdd(&g_cursor[dst[i]], 1); g_ssrc[p] = src[i]; }
}

// ===========================================================================
// Aggregation D=140: warp per dst node; online softmax, then float4 gather.
// ===========================================================================
__global__ void aggregate140_kernel(const float* __restrict__ h,
                                    const float* __restrict__ el,
                                    const float* __restrict__ er,
                                    const float* __restrict__ bias,
                                    float* __restrict__ out, int n)
{
    int w = (blockIdx.x * blockDim.x + threadIdx.x) >> 5;
    int lane = threadIdx.x & 31;
    if (w >= n) return;
    const int start = g_offs[w], end = g_offs[w + 1];
    const float er_i = er[w];

    float m = -1e30f, s = 0.f;
    for (int e = start + lane; e < end; e += 32) {
        int sj = g_ssrc[e];
        float v = el[sj] + er_i;
        v = (v > 0.f) ? v : 0.2f * v;
        float nm = fmaxf(m, v);
        s = s * __expf(m - nm) + __expf(v - nm);
        m = nm;
    }
    for (int o = 16; o; o >>= 1) {
        float om = __shfl_xor_sync(0xffffffffu, m, o);
        float os = __shfl_xor_sync(0xffffffffu, s, o);
        float nm = fmaxf(m, om);
        s = s * __expf(m - nm) + os * __expf(om - nm);
        m = nm;
    }
    const float inv = 1.f / s;

    float4 acc  = make_float4(0.f, 0.f, 0.f, 0.f);
    float4 accx = make_float4(0.f, 0.f, 0.f, 0.f);   // lanes 0-2: cols 128..139

    for (int e0 = start; e0 < end; e0 += 32) {
        int e = e0 + lane;
        int sj = 0; float a = 0.f;
        if (e < end) {
            sj = g_ssrc[e];
            float v = el[sj] + er_i;
            v = (v > 0.f) ? v : 0.2f * v;
            a = __expf(v - m) * inv;
        }
        int cnt = min(32, end - e0);
        for (int j = 0; j < cnt; ++j) {
            int   sje = __shfl_sync(0xffffffffu, sj, j);
            float aje = __shfl_sync(0xffffffffu, a, j);
            const float4* hp = (const float4*)(h + (size_t)sje * D_H);
            float4 v = hp[lane];
            acc.x += aje * v.x; acc.y += aje * v.y;
            acc.z += aje * v.z; acc.w += aje * v.w;
            if (lane < 3) {
                float4 v2 = hp[32 + lane];
                accx.x += aje * v2.x; accx.y += aje * v2.y;
                accx.z += aje * v2.z; accx.w += aje * v2.w;
            }
        }
    }

    const float4* b4 = (const float4*)bias;
    float4 bb = b4[lane];
    float4 r  = make_float4(fmaxf(acc.x + bb.x, 0.f), fmaxf(acc.y + bb.y, 0.f),
                            fmaxf(acc.z + bb.z, 0.f), fmaxf(acc.w + bb.w, 0.f));
    ((float4*)(out + (size_t)w * D_H))[lane] = r;
    if (lane < 3) {
        float4 bb2 = b4[32 + lane];
        float4 r2  = make_float4(fmaxf(accx.x + bb2.x, 0.f), fmaxf(accx.y + bb2.y, 0.f),
                                 fmaxf(accx.z + bb2.z, 0.f), fmaxf(accx.w + bb2.w, 0.f));
        ((float4*)(out + (size_t)w * D_H))[32 + lane] = r2;
    }
}

// ===========================================================================
// Aggregation D=7 (layer 1 output)
// ===========================================================================
__global__ void aggregate7_kernel(const float* __restrict__ h,
                                  const float* __restrict__ el,
                                  const float* __restrict__ er,
                                  const float* __restrict__ bias,
                                  float* __restrict__ out, int n)
{
    int w = (blockIdx.x * blockDim.x + threadIdx.x) >> 5;
    int lane = threadIdx.x & 31;
    if (w >= n) return;
    const int start = g_offs[w], end = g_offs[w + 1];
    const float er_i = er[w];

    float m = -1e30f, s = 0.f;
    for (int e = start + lane; e < end; e += 32) {
        int sj = g_ssrc[e];
        float v = el[sj] + er_i;
        v = (v > 0.f) ? v : 0.2f * v;
        float nm = fmaxf(m, v);
        s = s * __expf(m - nm) + __expf(v - nm);
        m = nm;
    }
    for (int o = 16; o; o >>= 1) {
        float om = __shfl_xor_sync(0xffffffffu, m, o);
        float os = __shfl_xor_sync(0xffffffffu, s, o);
        float nm = fmaxf(m, om);
        s = s * __expf(m - nm) + os * __expf(om - nm);
        m = nm;
    }
    const float inv = 1.f / s;

    float acc = 0.f;
    for (int e0 = start; e0 < end; e0 += 32) {
        int e = e0 + lane;
        int sj = 0; float a = 0.f;
        if (e < end) {
            sj = g_ssrc[e];
            float v = el[sj] + er_i;
            v = (v > 0.f) ? v : 0.2f * v;
            a = __expf(v - m) * inv;
        }
        int cnt = min(32, end - e0);
        for (int j = 0; j < cnt; ++j) {
            int   sje = __shfl_sync(0xffffffffu, sj, j);
            float aje = __shfl_sync(0xffffffffu, a, j);
            if (lane < D_O) acc += aje * h[(size_t)sje * D_O + lane];
        }
    }
    if (lane < D_O) out[(size_t)w * D_O + lane] = fmaxf(acc + bias[lane], 0.f);
}

// ===========================================================================
// Layer-1 projection (140 -> 7) + el1/er1
// ===========================================================================
__global__ void proj1_kernel(const float* __restrict__ h1, const float* __restrict__ W1,
                             const float* __restrict__ al1, const float* __restrict__ ar1,
                             float* __restrict__ h1p, float* __restrict__ el1,
                             float* __restrict__ er1, int n)
{
    __shared__ float Wt[D_O * D_H];
    __shared__ float als[D_O], ars[D_O];
    for (int i = threadIdx.x; i < D_H * D_O; i += blockDim.x) {
        int c = i / D_O, j = i % D_O;
        Wt[j * D_H + c] = W1[i];
    }
    if (threadIdx.x < D_O) { als[threadIdx.x] = al1[threadIdx.x]; ars[threadIdx.x] = ar1[threadIdx.x]; }
    __syncthreads();

    int w = (blockIdx.x * blockDim.x + threadIdx.x) >> 5;
    int lane = threadIdx.x & 31;
    if (w >= n) return;

    float p[D_O];
    #pragma unroll
    for (int j = 0; j < D_O; ++j) p[j] = 0.f;

    const float* hr = h1 + (size_t)w * D_H;
    for (int c = lane; c < D_H; c += 32) {
        float hc = hr[c];
        #pragma unroll
        for (int j = 0; j < D_O; ++j) p[j] += hc * Wt[j * D_H + c];
    }
    #pragma unroll
    for (int j = 0; j < D_O; ++j)
        for (int o = 16; o; o >>= 1) p[j] += __shfl_xor_sync(0xffffffffu, p[j], o);

    if (lane == 0) {
        float elv = 0.f, erv = 0.f;
        float* op = h1p + (size_t)w * D_O;
        #pragma unroll
        for (int j = 0; j < D_O; ++j) {
            op[j] = p[j];
            elv += p[j] * als[j];
            erv += p[j] * ars[j];
        }
        el1[w] = elv;
        er1[w] = erv;
    }
}

// ===========================================================================
// launch
// ===========================================================================
extern "C" void kernel_launch(void* const* d_in, const int* in_sizes, int n_in,
                              void* d_out, int out_size)
{
    const float* X = nullptr;  const int* src = nullptr; const int* dst = nullptr;
    const float* W0 = nullptr; const float* al0 = nullptr; const float* ar0 = nullptr;
    const float* b0 = nullptr; const float* W1 = nullptr; const float* al1 = nullptr;
    const float* ar1 = nullptr; const float* b1 = nullptr;

    for (int i = 0; i < n_in; ++i) {
        long long s = in_sizes[i];
        void* p = d_in[i];
        if      (s == (long long)MAXN * D_IN) X  = (const float*)p;
        else if (s == (long long)MAXE) { if (!src) src = (const int*)p; else dst = (const int*)p; }
        else if (s == (long long)D_IN * D_H) W0 = (const float*)p;
        else if (s == (long long)D_H * D_O)  W1 = (const float*)p;
        else if (s == D_H) { if (!al0) al0 = (const float*)p; else if (!ar0) ar0 = (const float*)p; else b0 = (const float*)p; }
        else if (s == D_O) { if (!al1) al1 = (const float*)p; else if (!ar1) ar1 = (const float*)p; else b1 = (const float*)p; }
    }
    if (!X || !src || !dst || !W0 || !al0 || !ar0 || !b0 || !W1 || !al1 || !ar1 || !b1) {
        X   = (const float*)d_in[0];  src = (const int*)d_in[1];  dst = (const int*)d_in[2];
        W0  = (const float*)d_in[3];  al0 = (const float*)d_in[4]; ar0 = (const float*)d_in[5];
        b0  = (const float*)d_in[6];  W1  = (const float*)d_in[7]; al1 = (const float*)d_in[8];
        ar1 = (const float*)d_in[9];  b1  = (const float*)d_in[10];
    }
    float* out = (float*)d_out;

    float *h0, *h1, *h1p, *el0, *er0, *el1, *er1;
    cudaGetSymbolAddress((void**)&h0,  g_h0);
    cudaGetSymbolAddress((void**)&h1,  g_h1);
    cudaGetSymbolAddress((void**)&h1p, g_h1p);
    cudaGetSymbolAddress((void**)&el0, g_el0);
    cudaGetSymbolAddress((void**)&er0, g_er0);
    cudaGetSymbolAddress((void**)&el1, g_el1);
    cudaGetSymbolAddress((void**)&er1, g_er1);

    const int N = [&]{
        for (int i = 0; i < n_in; ++i) if (in_sizes[i] % D_IN == 0 && in_sizes[i] > 1000000) return in_sizes[i] / D_IN;
        return MAXN; }();
    int E = MAXE;
    for (int i = 0; i < n_in; ++i) if ((const void*)d_in[i] == (const void*)src) { E = in_sizes[i]; break; }

    cudaFuncSetAttribute(gemm0_mma_kernel, cudaFuncAttributeMaxDynamicSharedMemorySize, SM_BYTES);

    const int TB = 256;
    const int nwarp_blocks = (N + 7) / 8;
    const int nch = (N + 1023) / 1024;

    // Harness inserts ~2 kernels before ours; ncu -s 5 lands on launch idx 3.
    prep_b_kernel<<<(NPAD * KPAD + 255) / 256, 256>>>(W0);                   // 0
    zero_all_kernel<<<(N + TB - 1) / TB, TB>>>(N);                           // 1
    count_kernel<<<(E + TB - 1) / TB, TB>>>(dst, E);                         // 2
    gemm0_mma_kernel<<<(N + 127) / 128, GT, SM_BYTES>>>(X, al0, ar0, N);     // 3 <- ncu
    scan_chunk_sums_kernel<<<nch, TB>>>(N);                                  // 4
    scan_partials_kernel<<<1, 32>>>(nch, N, E);                              // 5
    scan_final_kernel<<<nch, TB>>>(N);                                       // 6
    fill_kernel<<<(E + TB - 1) / TB, TB>>>(src, dst, E);                     // 7
    aggregate140_kernel<<<nwarp_blocks, TB>>>(h0, el0, er0, b0, h1, N);      // 8
    proj1_kernel<<<nwarp_blocks, TB>>>(h1, W1, al1, ar1, h1p, el1, er1, N);  // 9
    aggregate7_kernel<<<nwarp_blocks, TB>>>(h1p, el1, er1, b1, out, N);      // 10
}